// round 1
// baseline (speedup 1.0000x reference)
#include <cuda_runtime.h>
#include <math.h>

#define B_  4
#define S_  2048
#define D_  1024
#define H_  16
#define HD_ 64
#define M_  (B_ * S_)          // 8192 rows of x

// ---------------------------------------------------------------------------
// Scratch (allocation-free rule: __device__ globals)
// ---------------------------------------------------------------------------
__device__ float g_q[(size_t)B_ * H_ * S_ * HD_];     // [b][h][s][hd] 32 MB
__device__ float g_k[(size_t)B_ * H_ * S_ * HD_];
__device__ float g_v[(size_t)B_ * H_ * S_ * HD_];
__device__ float g_attn[(size_t)M_ * D_];             // [b*s][h*hd]   32 MB

// ---------------------------------------------------------------------------
// GEMM: C[M,N] = A[M,K] @ B[K,N] + bias[N]
//   EPI = 1 : A = param (x), epilogue scatters into g_q/g_k/g_v  (N = 3*D)
//   EPI = 2 : A = g_attn,    epilogue writes C directly          (N = D)
// 128x128 block tile, 256 threads, 8x8 per-thread (split 4+4), BK=8.
// ---------------------------------------------------------------------------
template <int EPI>
__global__ __launch_bounds__(256, 2)
void gemm128(const float* __restrict__ A, const float* __restrict__ Bm,
             const float* __restrict__ bias, float* __restrict__ C,
             int M, int N, int K)
{
    __shared__ float As[8][128];   // [k][m] (transposed)
    __shared__ float Bs[8][128];   // [k][n]

    const int tid = threadIdx.x;
    const int bm  = blockIdx.y * 128;
    const int bn  = blockIdx.x * 128;

    const int arow = tid >> 1;             // 128 rows, 2 threads/row
    const int acol = (tid & 1) * 4;
    const int brow = tid >> 5;             // 8 rows, 32 threads/row
    const int bcol = (tid & 31) * 4;

    const int tx = tid & 15;               // 16 col-groups
    const int ty = tid >> 4;               // 16 row-groups

    const float* Asrc = (EPI == 2) ? (const float*)g_attn : A;

    float acc[8][8];
#pragma unroll
    for (int i = 0; i < 8; i++)
#pragma unroll
        for (int j = 0; j < 8; j++) acc[i][j] = 0.f;

    const float* Aptr = Asrc + (size_t)(bm + arow) * K + acol;
    const float* Bptr = Bm + (size_t)brow * N + bn + bcol;

    for (int k0 = 0; k0 < K; k0 += 8) {
        float4 av = *(const float4*)(Aptr + k0);
        float4 bv = *(const float4*)(Bptr + (size_t)k0 * N);
        As[acol + 0][arow] = av.x;
        As[acol + 1][arow] = av.y;
        As[acol + 2][arow] = av.z;
        As[acol + 3][arow] = av.w;
        *(float4*)&Bs[brow][bcol] = bv;
        __syncthreads();

#pragma unroll
        for (int kk = 0; kk < 8; kk++) {
            float4 a0 = *(const float4*)&As[kk][ty * 4];
            float4 a1 = *(const float4*)&As[kk][64 + ty * 4];
            float4 b0 = *(const float4*)&Bs[kk][tx * 4];
            float4 b1 = *(const float4*)&Bs[kk][64 + tx * 4];
            float af[8] = {a0.x, a0.y, a0.z, a0.w, a1.x, a1.y, a1.z, a1.w};
            float bf[8] = {b0.x, b0.y, b0.z, b0.w, b1.x, b1.y, b1.z, b1.w};
#pragma unroll
            for (int i = 0; i < 8; i++)
#pragma unroll
                for (int j = 0; j < 8; j++)
                    acc[i][j] += af[i] * bf[j];
        }
        __syncthreads();
    }

#pragma unroll
    for (int i = 0; i < 8; i++) {
        int row = bm + ((i < 4) ? (ty * 4 + i) : (64 + ty * 4 + i - 4));
#pragma unroll
        for (int jh = 0; jh < 2; jh++) {
            int n0 = bn + ((jh == 0) ? (tx * 4) : (64 + tx * 4));
            float4 v;
            v.x = acc[i][jh * 4 + 0] + bias[n0 + 0];
            v.y = acc[i][jh * 4 + 1] + bias[n0 + 1];
            v.z = acc[i][jh * 4 + 2] + bias[n0 + 2];
            v.w = acc[i][jh * 4 + 3] + bias[n0 + 3];
            if (EPI == 2) {
                *(float4*)(C + (size_t)row * N + n0) = v;
            } else {
                // scatter into q/k/v [b][h][s][hd]; 4-col chunk never crosses
                // a head (64) or a q/k/v (1024) boundary.
                int which = n0 >> 10;          // 0/1/2
                int d     = n0 & 1023;
                int h     = d >> 6;
                int hd    = d & 63;
                int b     = row >> 11;         // / 2048
                int srow  = row & 2047;
                float* dst = (which == 0) ? g_q : (which == 1) ? g_k : g_v;
                size_t idx = ((((size_t)b * H_ + h) * S_ + srow) * HD_) + hd;
                *(float4*)(dst + idx) = v;
            }
        }
    }
}

// ---------------------------------------------------------------------------
// Flash attention, fp32, HD=64.
// Grid: (S/64, B*H). 128 threads. Each thread owns a 4(q) x 8(col) sub-tile.
// smem: Qt [d][qr], Kt [d][kc] (reused as Pt [kc][qr]), Vs [kc][oc] = 48 KB.
// XOR swizzle on the qr/kc column-group index (keyed by row>>2) kills the
// 16-way transpose-store conflicts while keeping all reads single float4s.
// ---------------------------------------------------------------------------
__device__ __forceinline__ int swz(int row, int colgrp)
{
    return (colgrp ^ ((row >> 2) & 15)) << 2;   // float offset within 64-wide row
}

__global__ __launch_bounds__(128, 4)
void attn64()
{
    __shared__ float Qt[64][64];   // [d][qr], swizzled
    __shared__ float Kt[64][64];   // [d][kc], swizzled; reused as Pt[kc][qr]
    __shared__ float Vs[64][64];   // [kc][oc], plain

    const int tid = threadIdx.x;
    const int bh  = blockIdx.y;            // 0..63  (b*H + h)
    const int q0  = blockIdx.x * 64;

    const float* Qp = g_q + (size_t)bh * S_ * HD_;
    const float* Kp = g_k + (size_t)bh * S_ * HD_;
    const float* Vp = g_v + (size_t)bh * S_ * HD_;

    // ---- load Q tile transposed (swizzled) ----
    for (int i = tid; i < 64 * 16; i += 128) {
        int r  = i >> 4;
        int c4 = (i & 15) * 4;
        float4 v = *(const float4*)(Qp + (size_t)(q0 + r) * HD_ + c4);
        int rg4 = r >> 2, rr = r & 3;
        Qt[c4 + 0][swz(c4 + 0, rg4) + rr] = v.x;
        Qt[c4 + 1][swz(c4 + 1, rg4) + rr] = v.y;
        Qt[c4 + 2][swz(c4 + 2, rg4) + rr] = v.z;
        Qt[c4 + 3][swz(c4 + 3, rg4) + rr] = v.w;
    }

    const int rg = tid >> 3;   // 0..15 -> q rows rg*4 .. rg*4+3
    const int cg = tid & 7;    // 0..7  -> cols  cg*8 .. cg*8+7

    float m[4], l[4], o[4][8];
#pragma unroll
    for (int r = 0; r < 4; r++) {
        m[r] = -1e30f; l[r] = 0.f;
#pragma unroll
        for (int c = 0; c < 8; c++) o[r][c] = 0.f;
    }

    for (int kt = 0; kt < S_ / 64; kt++) {
        const int k0 = kt * 64;
        __syncthreads();   // prior PV / Q-load visible before overwrite
        // ---- load K (transposed+swizzled) and V (plain) ----
        for (int i = tid; i < 64 * 16; i += 128) {
            int r  = i >> 4;
            int c4 = (i & 15) * 4;
            float4 kv = *(const float4*)(Kp + (size_t)(k0 + r) * HD_ + c4);
            int rg4 = r >> 2, rr = r & 3;
            Kt[c4 + 0][swz(c4 + 0, rg4) + rr] = kv.x;
            Kt[c4 + 1][swz(c4 + 1, rg4) + rr] = kv.y;
            Kt[c4 + 2][swz(c4 + 2, rg4) + rr] = kv.z;
            Kt[c4 + 3][swz(c4 + 3, rg4) + rr] = kv.w;
            float4 vv = *(const float4*)(Vp + (size_t)(k0 + r) * HD_ + c4);
            *(float4*)&Vs[r][c4] = vv;
        }
        __syncthreads();

        // ---- S = (Q K^T) * 1/sqrt(64) ----
        float s[4][8];
#pragma unroll
        for (int r = 0; r < 4; r++)
#pragma unroll
            for (int c = 0; c < 8; c++) s[r][c] = 0.f;

#pragma unroll 4
        for (int d = 0; d < 64; d++) {
            float4 q4  = *(const float4*)&Qt[d][swz(d, rg)];
            float4 ka  = *(const float4*)&Kt[d][swz(d, cg * 2)];
            float4 kb  = *(const float4*)&Kt[d][swz(d, cg * 2 + 1)];
            float qa[4] = {q4.x, q4.y, q4.z, q4.w};
            float kk[8] = {ka.x, ka.y, ka.z, ka.w, kb.x, kb.y, kb.z, kb.w};
#pragma unroll
            for (int r = 0; r < 4; r++)
#pragma unroll
                for (int c = 0; c < 8; c++)
                    s[r][c] += qa[r] * kk[c];
        }

        // ---- online softmax update (per row; 8 lanes share each row) ----
#pragma unroll
        for (int r = 0; r < 4; r++) {
            float tm = -1e30f;
#pragma unroll
            for (int c = 0; c < 8; c++) {
                s[r][c] *= 0.125f;
                tm = fmaxf(tm, s[r][c]);
            }
            tm = fmaxf(tm, __shfl_xor_sync(0xffffffffu, tm, 1));
            tm = fmaxf(tm, __shfl_xor_sync(0xffffffffu, tm, 2));
            tm = fmaxf(tm, __shfl_xor_sync(0xffffffffu, tm, 4));
            float mn   = fmaxf(m[r], tm);
            float corr = __expf(m[r] - mn);
            float ps = 0.f;
#pragma unroll
            for (int c = 0; c < 8; c++) {
                float p = __expf(s[r][c] - mn);
                s[r][c] = p;
                ps += p;
            }
            ps += __shfl_xor_sync(0xffffffffu, ps, 1);
            ps += __shfl_xor_sync(0xffffffffu, ps, 2);
            ps += __shfl_xor_sync(0xffffffffu, ps, 4);
            l[r] = l[r] * corr + ps;
            m[r] = mn;
#pragma unroll
            for (int c = 0; c < 8; c++) o[r][c] *= corr;
        }

        __syncthreads();   // S-compute reads of Kt done before Pt overwrite

        // ---- write P transposed: Pt[kc][qr] (into Kt storage, swizzled) ----
#pragma unroll
        for (int c = 0; c < 8; c++) {
            int kc = cg * 8 + c;
            float4 pv = make_float4(s[0][c], s[1][c], s[2][c], s[3][c]);
            *(float4*)&Kt[kc][swz(kc, rg)] = pv;
        }
        __syncthreads();

        // ---- O += P @ V ----
#pragma unroll 4
        for (int kc = 0; kc < 64; kc++) {
            float4 p4 = *(const float4*)&Kt[kc][swz(kc, rg)];
            float4 va = *(const float4*)&Vs[kc][cg * 8];
            float4 vb = *(const float4*)&Vs[kc][cg * 8 + 4];
            float pa[4] = {p4.x, p4.y, p4.z, p4.w};
            float vv[8] = {va.x, va.y, va.z, va.w, vb.x, vb.y, vb.z, vb.w};
#pragma unroll
            for (int r = 0; r < 4; r++)
#pragma unroll
                for (int c = 0; c < 8; c++)
                    o[r][c] += pa[r] * vv[c];
        }
    }

    // ---- normalize and write to g_attn [b][s][h*64+oc] ----
    const int b = bh >> 4;
    const int h = bh & 15;
#pragma unroll
    for (int r = 0; r < 4; r++) {
        float inv = 1.f / l[r];
        int srow = q0 + rg * 4 + r;
        size_t base = ((size_t)(b * S_ + srow)) * D_ + h * 64 + cg * 8;
        float4 o0 = make_float4(o[r][0] * inv, o[r][1] * inv,
                                o[r][2] * inv, o[r][3] * inv);
        float4 o1 = make_float4(o[r][4] * inv, o[r][5] * inv,
                                o[r][6] * inv, o[r][7] * inv);
        *(float4*)(g_attn + base)     = o0;
        *(float4*)(g_attn + base + 4) = o1;
    }
}

// ---------------------------------------------------------------------------
extern "C" void kernel_launch(void* const* d_in, const int* in_sizes, int n_in,
                              void* d_out, int out_size)
{
    const float* x     = (const float*)d_in[0];
    const float* w_qkv = (const float*)d_in[1];
    const float* b_qkv = (const float*)d_in[2];
    const float* w_out = (const float*)d_in[3];
    const float* b_out = (const float*)d_in[4];
    float* out = (float*)d_out;

    // 1) QKV projection -> scatter q/k/v [B,H,S,HD]
    {
        dim3 grid((3 * D_) / 128, M_ / 128);   // 24 x 64
        gemm128<1><<<grid, 256>>>(x, w_qkv, b_qkv, nullptr, M_, 3 * D_, D_);
    }
    // 2) flash attention -> g_attn [B,S,D]
    {
        dim3 grid(S_ / 64, B_ * H_);           // 32 x 64
        attn64<<<grid, 128>>>();
    }
    // 3) output projection
    {
        dim3 grid(D_ / 128, M_ / 128);         // 8 x 64
        gemm128<2><<<grid, 256>>>(nullptr, w_out, b_out, out, M_, D_, D_);
    }
}

// round 3
// speedup vs baseline: 1.3609x; 1.3609x over previous
#include <cuda_runtime.h>
#include <mma.h>
#include <math.h>

using namespace nvcuda;

#define B_  4
#define S_  2048
#define D_  1024
#define H_  16
#define HD_ 64
#define M_  (B_ * S_)

// ---------------------------------------------------------------------------
// Scratch (allocation-free rule: __device__ globals)
// ---------------------------------------------------------------------------
__device__ float g_q[(size_t)B_ * H_ * S_ * HD_];     // [b][h][s][hd]
__device__ float g_k[(size_t)B_ * H_ * S_ * HD_];
__device__ float g_v[(size_t)B_ * H_ * S_ * HD_];
__device__ float g_attn[(size_t)M_ * D_];             // [b*s][h*hd]

typedef wmma::fragment<wmma::matrix_a, 16, 16, 8, wmma::precision::tf32, wmma::row_major> AFrag;
typedef wmma::fragment<wmma::matrix_b, 16, 16, 8, wmma::precision::tf32, wmma::row_major> BFragR;
typedef wmma::fragment<wmma::matrix_b, 16, 16, 8, wmma::precision::tf32, wmma::col_major> BFragC;
typedef wmma::fragment<wmma::accumulator, 16, 16, 8, float> CFrag;

template <class F>
__device__ __forceinline__ void to_tf32(F& f)
{
#pragma unroll
    for (int t = 0; t < f.num_elements; t++)
        f.x[t] = wmma::__float_to_tf32(f.x[t]);
}

// ---------------------------------------------------------------------------
// tf32 tensor-core GEMM: C[M,N] = A[M,K] @ B[K,N] + bias
//   EPI=1 : epilogue scatters into g_q/g_k/g_v (N = 3*D)
//   EPI=2 : epilogue writes C directly         (N = D)
// 128x128 block, 8 warps, warp tile 64x32 (4x2 wmma tiles), BK=16.
// ---------------------------------------------------------------------------
template <int EPI>
__global__ __launch_bounds__(256)
void gemm_tc(const float* __restrict__ A, const float* __restrict__ Bm,
             const float* __restrict__ bias, float* __restrict__ C,
             int M, int N, int K)
{
    __shared__ float As[128][20];     // [m][k], ld=20
    __shared__ float Bs[16][132];     // [k][n], ld=132
    __shared__ float stage[8][16][16];

    const int tid  = threadIdx.x;
    const int warp = tid >> 5;
    const int lane = tid & 31;
    const int wm   = warp >> 2;       // 0..1 -> m offset *64
    const int wn   = warp & 3;        // 0..3 -> n offset *32
    const int bm   = blockIdx.y * 128;
    const int bn   = blockIdx.x * 128;

    const float* Asrc = (EPI == 2) ? (const float*)g_attn : A;

    CFrag acc[4][2];
#pragma unroll
    for (int i = 0; i < 4; i++)
#pragma unroll
        for (int j = 0; j < 2; j++) wmma::fill_fragment(acc[i][j], 0.f);

    const int ar = tid >> 2;              // 0..63
    const int ac = (tid & 3) << 2;        // 0,4,8,12

    for (int k0 = 0; k0 < K; k0 += 16) {
        // A tile 128x16
        {
            float4 v0 = *(const float4*)(Asrc + (size_t)(bm + ar) * K + k0 + ac);
            float4 v1 = *(const float4*)(Asrc + (size_t)(bm + ar + 64) * K + k0 + ac);
            *(float4*)&As[ar][ac]      = v0;
            *(float4*)&As[ar + 64][ac] = v1;
        }
        // B tile 16x128
#pragma unroll
        for (int p = 0; p < 2; p++) {
            int i  = tid + p * 256;
            int r  = i >> 5;
            int c4 = (i & 31) << 2;
            float4 v = *(const float4*)(Bm + (size_t)(k0 + r) * N + bn + c4);
            *(float4*)&Bs[r][c4] = v;
        }
        __syncthreads();

#pragma unroll
        for (int ks = 0; ks < 2; ks++) {
            const int kk = ks * 8;
            AFrag a[4];
            BFragR b[2];
#pragma unroll
            for (int mi = 0; mi < 4; mi++) {
                wmma::load_matrix_sync(a[mi], &As[wm * 64 + mi * 16][kk], 20);
                to_tf32(a[mi]);
            }
#pragma unroll
            for (int ni = 0; ni < 2; ni++) {
                wmma::load_matrix_sync(b[ni], &Bs[kk][wn * 32 + ni * 16], 132);
                to_tf32(b[ni]);
            }
#pragma unroll
            for (int mi = 0; mi < 4; mi++)
#pragma unroll
                for (int ni = 0; ni < 2; ni++)
                    wmma::mma_sync(acc[mi][ni], a[mi], b[ni], acc[mi][ni]);
        }
        __syncthreads();
    }

    // epilogue: stage each 16x16 tile through smem
    const int sr = lane >> 1;
    const int sc = (lane & 1) * 8;
#pragma unroll
    for (int mi = 0; mi < 4; mi++) {
#pragma unroll
        for (int ni = 0; ni < 2; ni++) {
            wmma::store_matrix_sync(&stage[warp][0][0], acc[mi][ni], 16, wmma::mem_row_major);
            __syncwarp();
            int row  = bm + wm * 64 + mi * 16 + sr;
            int col0 = bn + wn * 32 + ni * 16 + sc;
            float v[8];
#pragma unroll
            for (int c = 0; c < 8; c++)
                v[c] = stage[warp][sr][sc + c] + bias[col0 + c];
            if (EPI == 2) {
                *(float4*)(C + (size_t)row * N + col0)     = make_float4(v[0], v[1], v[2], v[3]);
                *(float4*)(C + (size_t)row * N + col0 + 4) = make_float4(v[4], v[5], v[6], v[7]);
            } else {
                int which = col0 >> 10;
                int d     = col0 & 1023;
                int h     = d >> 6;
                int hd    = d & 63;
                int b     = row >> 11;
                int srow  = row & 2047;
                float* dst = (which == 0) ? g_q : (which == 1) ? g_k : g_v;
                size_t idx = ((((size_t)b * H_ + h) * S_ + srow) * HD_) + hd;
                *(float4*)(dst + idx)     = make_float4(v[0], v[1], v[2], v[3]);
                *(float4*)(dst + idx + 4) = make_float4(v[4], v[5], v[6], v[7]);
            }
            __syncwarp();
        }
    }
}

// ---------------------------------------------------------------------------
// Flash attention with tf32 wmma. Q tile 128, KV tile 64, HD=64.
// 8 warps / 256 threads; warp w owns q rows [w*16, w*16+16).
// Dynamic smem: Qs[128][72] Ks[64][72] Vs[64][72] Ss[128][72] Os[128][72] m l
// ---------------------------------------------------------------------------
#define LDA 72
#define QOFF 0
#define KOFF (128 * LDA)
#define VOFF (KOFF + 64 * LDA)
#define SOFF (VOFF + 64 * LDA)
#define OOFF (SOFF + 128 * LDA)
#define MOFF (OOFF + 128 * LDA)
#define LOFF (MOFF + 128)
#define ATT_SMEM ((LOFF + 128) * 4)

__global__ __launch_bounds__(256)
void attn_tc()
{
    extern __shared__ float sm[];
    float* Qs = sm + QOFF;
    float* Ks = sm + KOFF;
    float* Vs = sm + VOFF;
    float* Ss = sm + SOFF;
    float* Os = sm + OOFF;
    float* ms = sm + MOFF;
    float* ls = sm + LOFF;

    const int tid  = threadIdx.x;
    const int warp = tid >> 5;
    const int bh   = blockIdx.y;
    const int q0   = blockIdx.x * 128;

    const float* Qp = g_q + (size_t)bh * S_ * HD_;
    const float* Kp = g_k + (size_t)bh * S_ * HD_;
    const float* Vp = g_v + (size_t)bh * S_ * HD_;

    // load Q tile, zero O, init m/l
#pragma unroll
    for (int p = 0; p < 8; p++) {
        int i  = tid + p * 256;
        int r  = i >> 4;
        int c4 = (i & 15) << 2;
        float4 v = *(const float4*)(Qp + (size_t)(q0 + r) * HD_ + c4);
        *(float4*)&Qs[r * LDA + c4] = v;
    }
    for (int i = tid; i < 128 * LDA; i += 256) Os[i] = 0.f;
    if (tid < 128) { ms[tid] = -1e30f; ls[tid] = 0.f; }
    __syncthreads();

    // cache Q fragments (constant across kv tiles)
    AFrag qa[8];
#pragma unroll
    for (int ks = 0; ks < 8; ks++) {
        wmma::load_matrix_sync(qa[ks], &Qs[warp * 16 * LDA + ks * 8], LDA);
        to_tf32(qa[ks]);
    }

    const int row  = tid >> 1;
    const int half = tid & 1;

    for (int kt = 0; kt < S_ / 64; kt++) {
        const int k0 = kt * 64;
        __syncthreads();   // prev PV done before K/V overwrite
        // load K, V tiles (64x64)
#pragma unroll
        for (int p = 0; p < 4; p++) {
            int i  = tid + p * 256;
            int r  = i >> 4;
            int c4 = (i & 15) << 2;
            float4 kv = *(const float4*)(Kp + (size_t)(k0 + r) * HD_ + c4);
            float4 vv = *(const float4*)(Vp + (size_t)(k0 + r) * HD_ + c4);
            *(float4*)&Ks[r * LDA + c4] = kv;
            *(float4*)&Vs[r * LDA + c4] = vv;
        }
        __syncthreads();

        // S = Q @ K^T  (K^T as col_major fragment over Ks[kc][d])
#pragma unroll
        for (int nt = 0; nt < 4; nt++) {
            CFrag acc;
            wmma::fill_fragment(acc, 0.f);
#pragma unroll
            for (int ks = 0; ks < 8; ks++) {
                BFragC b;
                wmma::load_matrix_sync(b, &Ks[nt * 16 * LDA + ks * 8], LDA);
                to_tf32(b);
                wmma::mma_sync(acc, qa[ks], b, acc);
            }
            wmma::store_matrix_sync(&Ss[warp * 16 * LDA + nt * 16], acc, LDA, wmma::mem_row_major);
        }
        __syncthreads();

        // online softmax: 2 threads per row, 32 cols each
        {
            float* sr = Ss + row * LDA + half * 32;
            float mold = ms[row];
            float lold = ls[row];
            float tm = -1e30f;
#pragma unroll
            for (int i = 0; i < 8; i++) {
                float4 x = *(float4*)(sr + i * 4);
                x.x *= 0.125f; x.y *= 0.125f; x.z *= 0.125f; x.w *= 0.125f;
                *(float4*)(sr + i * 4) = x;
                tm = fmaxf(tm, fmaxf(fmaxf(x.x, x.y), fmaxf(x.z, x.w)));
            }
            tm = fmaxf(tm, __shfl_xor_sync(0xffffffffu, tm, 1));
            float mn   = fmaxf(mold, tm);
            float corr = __expf(mold - mn);
            float ps = 0.f;
#pragma unroll
            for (int i = 0; i < 8; i++) {
                float4 x = *(float4*)(sr + i * 4);
                x.x = __expf(x.x - mn); x.y = __expf(x.y - mn);
                x.z = __expf(x.z - mn); x.w = __expf(x.w - mn);
                *(float4*)(sr + i * 4) = x;
                ps += x.x + x.y + x.z + x.w;
            }
            ps += __shfl_xor_sync(0xffffffffu, ps, 1);
            if (!half) { ms[row] = mn; ls[row] = lold * corr + ps; }
            // rescale O row
            float* orow = Os + row * LDA + half * 32;
#pragma unroll
            for (int i = 0; i < 8; i++) {
                float4 x = *(float4*)(orow + i * 4);
                x.x *= corr; x.y *= corr; x.z *= corr; x.w *= corr;
                *(float4*)(orow + i * 4) = x;
            }
        }
        __syncthreads();

        // O += P @ V
        AFrag pa[8];
#pragma unroll
        for (int ks = 0; ks < 8; ks++) {
            wmma::load_matrix_sync(pa[ks], &Ss[warp * 16 * LDA + ks * 8], LDA);
            to_tf32(pa[ks]);
        }
#pragma unroll
        for (int nt = 0; nt < 4; nt++) {
            CFrag c;
            wmma::load_matrix_sync(c, &Os[warp * 16 * LDA + nt * 16], LDA, wmma::mem_row_major);
#pragma unroll
            for (int ks = 0; ks < 8; ks++) {
                BFragR b;
                wmma::load_matrix_sync(b, &Vs[ks * 8 * LDA + nt * 16], LDA);
                to_tf32(b);
                wmma::mma_sync(c, pa[ks], b, c);
            }
            wmma::store_matrix_sync(&Os[warp * 16 * LDA + nt * 16], c, LDA, wmma::mem_row_major);
        }
    }
    __syncthreads();

    // normalize + write to g_attn [b][s][h*64+c]
    const int b = bh >> 4;
    const int h = bh & 15;
    {
        float inv = 1.f / ls[row];
        size_t base = ((size_t)(b * S_ + q0 + row)) * D_ + h * 64 + half * 32;
        float* orow = Os + row * LDA + half * 32;
#pragma unroll
        for (int i = 0; i < 8; i++) {
            float4 x = *(float4*)(orow + i * 4);
            x.x *= inv; x.y *= inv; x.z *= inv; x.w *= inv;
            *(float4*)(g_attn + base + i * 4) = x;
        }
    }
}

// ---------------------------------------------------------------------------
extern "C" void kernel_launch(void* const* d_in, const int* in_sizes, int n_in,
                              void* d_out, int out_size)
{
    const float* x     = (const float*)d_in[0];
    const float* w_qkv = (const float*)d_in[1];
    const float* b_qkv = (const float*)d_in[2];
    const float* w_out = (const float*)d_in[3];
    const float* b_out = (const float*)d_in[4];
    float* out = (float*)d_out;

    cudaFuncSetAttribute(attn_tc, cudaFuncAttributeMaxDynamicSharedMemorySize, ATT_SMEM);

    // 1) QKV projection -> q/k/v [B,H,S,HD]
    {
        dim3 grid((3 * D_) / 128, M_ / 128);   // 24 x 64
        gemm_tc<1><<<grid, 256>>>(x, w_qkv, b_qkv, nullptr, M_, 3 * D_, D_);
    }
    // 2) flash attention -> g_attn [B,S,D]
    {
        dim3 grid(S_ / 128, B_ * H_);          // 16 x 64
        attn_tc<<<grid, 256, ATT_SMEM>>>();
    }
    // 3) output projection
    {
        dim3 grid(D_ / 128, M_ / 128);         // 8 x 64
        gemm_tc<2><<<grid, 256>>>(nullptr, w_out, b_out, out, M_, D_, D_);
    }
}

// round 4
// speedup vs baseline: 2.3190x; 1.7040x over previous
#include <cuda_runtime.h>
#include <mma.h>
#include <math.h>
#include <stdint.h>

using namespace nvcuda;

#define B_  4
#define S_  2048
#define D_  1024
#define H_  16
#define HD_ 64
#define M_  (B_ * S_)
#define NT_ (S_ / 64)          // 32 kv tiles

// ---------------------------------------------------------------------------
// Scratch (__device__ globals; allocation-free rule)
// ---------------------------------------------------------------------------
__device__ float g_q[(size_t)B_ * H_ * S_ * HD_];      // tf32-rounded
__device__ float g_k[(size_t)B_ * H_ * S_ * HD_];
__device__ float g_v[(size_t)B_ * H_ * S_ * HD_];
__device__ float g_attn[(size_t)M_ * D_];              // tf32-rounded
__device__ float g_xr[(size_t)M_ * D_];                // rounded copies
__device__ float g_wqkvr[(size_t)D_ * 3 * D_];
__device__ float g_woutr[(size_t)D_ * D_];

// ---------------------------------------------------------------------------
// helpers
// ---------------------------------------------------------------------------
__device__ __forceinline__ float tf32r(float x)
{
    float y;
    asm("cvt.rna.tf32.f32 %0, %1;" : "=f"(y) : "f"(x));
    return y;
}

__device__ __forceinline__ uint32_t saddr(const void* p)
{
    return (uint32_t)__cvta_generic_to_shared(p);
}

__device__ __forceinline__ void cpa16(uint32_t dst, const void* src)
{
    asm volatile("cp.async.cg.shared.global [%0], [%1], 16;\n" :: "r"(dst), "l"(src));
}

#define CP_COMMIT() asm volatile("cp.async.commit_group;\n")
#define CP_WAIT1()  asm volatile("cp.async.wait_group 1;\n")
#define CP_WAIT0()  asm volatile("cp.async.wait_group 0;\n")

__device__ __forceinline__ void mma_tf32(float* c, const uint32_t* a,
                                         uint32_t b0, uint32_t b1)
{
    asm volatile(
        "mma.sync.aligned.m16n8k8.row.col.f32.tf32.tf32.f32 "
        "{%0,%1,%2,%3}, {%4,%5,%6,%7}, {%8,%9}, {%0,%1,%2,%3};"
        : "+f"(c[0]), "+f"(c[1]), "+f"(c[2]), "+f"(c[3])
        : "r"(a[0]), "r"(a[1]), "r"(a[2]), "r"(a[3]), "r"(b0), "r"(b1));
}

// ---------------------------------------------------------------------------
// pre-round inputs to tf32 (RN) into scratch
// ---------------------------------------------------------------------------
__global__ void round_sel(const float* __restrict__ src, int which, int n4)
{
    float* dst = (which == 0) ? g_xr : (which == 1) ? g_wqkvr : g_woutr;
    for (int i = blockIdx.x * blockDim.x + threadIdx.x; i < n4;
         i += gridDim.x * blockDim.x) {
        float4 v = ((const float4*)src)[i];
        v.x = tf32r(v.x); v.y = tf32r(v.y); v.z = tf32r(v.z); v.w = tf32r(v.w);
        ((float4*)dst)[i] = v;
    }
}

// ---------------------------------------------------------------------------
// tf32 wmma GEMM with cp.async double buffering.
//   EPI=1 : A=g_xr,  B=g_wqkvr, epilogue rounds + scatters to g_q/g_k/g_v
//   EPI=2 : A=g_attn,B=g_woutr, epilogue writes C (fp32)
// 128x128 block, 8 warps, warp 64x32, BK=16.
// ---------------------------------------------------------------------------
typedef wmma::fragment<wmma::matrix_a, 16, 16, 8, wmma::precision::tf32, wmma::row_major> AFrag;
typedef wmma::fragment<wmma::matrix_b, 16, 16, 8, wmma::precision::tf32, wmma::row_major> BFragR;
typedef wmma::fragment<wmma::accumulator, 16, 16, 8, float> CFrag;

template <int EPI>
__global__ __launch_bounds__(256)
void gemm_tc(const float* __restrict__ bias, float* __restrict__ C,
             int M, int N, int K)
{
    __shared__ float As[2][128][20];
    __shared__ float Bs[2][16][132];
    __shared__ float stage[8][16][16];

    const float* A  = (EPI == 1) ? g_xr : g_attn;
    const float* Bm = (EPI == 1) ? g_wqkvr : g_woutr;

    const int tid  = threadIdx.x;
    const int warp = tid >> 5;
    const int lane = tid & 31;
    const int wm   = warp >> 2;
    const int wn   = warp & 3;
    const int bm   = blockIdx.y * 128;
    const int bn   = blockIdx.x * 128;

    CFrag acc[4][2];
#pragma unroll
    for (int i = 0; i < 4; i++)
#pragma unroll
        for (int j = 0; j < 2; j++) wmma::fill_fragment(acc[i][j], 0.f);

    const int ITERS = K / 16;

    auto load_tiles = [&](int k0, int buf) {
        // A tile 128x16 : 512 16B chunks
#pragma unroll
        for (int p = 0; p < 2; p++) {
            int id = tid + p * 256;
            int r  = id >> 2;
            int c4 = (id & 3) << 2;
            cpa16(saddr(&As[buf][r][c4]), A + (size_t)(bm + r) * K + k0 + c4);
        }
        // B tile 16x128 : 512 16B chunks
#pragma unroll
        for (int p = 0; p < 2; p++) {
            int id = tid + p * 256;
            int r  = id >> 5;
            int c4 = (id & 31) << 2;
            cpa16(saddr(&Bs[buf][r][c4]), Bm + (size_t)(k0 + r) * N + bn + c4);
        }
    };

    load_tiles(0, 0);
    CP_COMMIT();

    for (int it = 0; it < ITERS; it++) {
        if (it + 1 < ITERS) {
            load_tiles((it + 1) * 16, (it + 1) & 1);
            CP_COMMIT();
            CP_WAIT1();
        } else {
            CP_WAIT0();
        }
        __syncthreads();

        const int buf = it & 1;
#pragma unroll
        for (int ks = 0; ks < 2; ks++) {
            const int kk = ks * 8;
            AFrag a[4];
            BFragR b[2];
#pragma unroll
            for (int mi = 0; mi < 4; mi++)
                wmma::load_matrix_sync(a[mi], &As[buf][wm * 64 + mi * 16][kk], 20);
#pragma unroll
            for (int ni = 0; ni < 2; ni++)
                wmma::load_matrix_sync(b[ni], &Bs[buf][kk][wn * 32 + ni * 16], 132);
#pragma unroll
            for (int mi = 0; mi < 4; mi++)
#pragma unroll
                for (int ni = 0; ni < 2; ni++)
                    wmma::mma_sync(acc[mi][ni], a[mi], b[ni], acc[mi][ni]);
        }
        __syncthreads();
    }

    // epilogue
    const int sr = lane >> 1;
    const int sc = (lane & 1) * 8;
#pragma unroll
    for (int mi = 0; mi < 4; mi++) {
#pragma unroll
        for (int ni = 0; ni < 2; ni++) {
            wmma::store_matrix_sync(&stage[warp][0][0], acc[mi][ni], 16, wmma::mem_row_major);
            __syncwarp();
            int row  = bm + wm * 64 + mi * 16 + sr;
            int col0 = bn + wn * 32 + ni * 16 + sc;
            float v[8];
#pragma unroll
            for (int c = 0; c < 8; c++)
                v[c] = stage[warp][sr][sc + c] + bias[col0 + c];
            if (EPI == 2) {
                *(float4*)(C + (size_t)row * N + col0)     = make_float4(v[0], v[1], v[2], v[3]);
                *(float4*)(C + (size_t)row * N + col0 + 4) = make_float4(v[4], v[5], v[6], v[7]);
            } else {
#pragma unroll
                for (int c = 0; c < 8; c++) v[c] = tf32r(v[c]);
                int which = col0 >> 10;
                int d     = col0 & 1023;
                int h     = d >> 6;
                int hd    = d & 63;
                int b     = row >> 11;
                int srow  = row & 2047;
                float* dst = (which == 0) ? g_q : (which == 1) ? g_k : g_v;
                size_t idx = ((((size_t)b * H_ + h) * S_ + srow) * HD_) + hd;
                *(float4*)(dst + idx)     = make_float4(v[0], v[1], v[2], v[3]);
                *(float4*)(dst + idx + 4) = make_float4(v[4], v[5], v[6], v[7]);
            }
            __syncwarp();
        }
    }
}

// ---------------------------------------------------------------------------
// Flash attention, mma.sync m16n8k8 tf32. Q tile 128, KV tile 64, HD 64.
// 8 warps; warp owns q rows [warp*16, warp*16+16). O resident in registers.
// Dyn smem: Ks[2][64][68] Vs[2][64][68] Ps[128][68]  (104448 B, 2 CTAs/SM)
// ---------------------------------------------------------------------------
#define LDS_ 68
#define KV_TILE_F (64 * LDS_)

__global__ __launch_bounds__(256, 2)
void attn_mma()
{
    extern __shared__ float sm[];
    float* KsB = sm;                       // [2][64][68]
    float* VsB = sm + 2 * KV_TILE_F;       // [2][64][68]
    float* Ps  = sm + 4 * KV_TILE_F;       // [128][68]

    const int tid  = threadIdx.x;
    const int warp = tid >> 5;
    const int lane = tid & 31;
    const int g    = lane >> 2;            // 0..7
    const int c    = lane & 3;             // 0..3
    const int bh   = blockIdx.y;
    const int q0   = blockIdx.x * 128;

    const float* Qp = g_q + (size_t)bh * S_ * HD_;
    const float* Kp = g_k + (size_t)bh * S_ * HD_;
    const float* Vp = g_v + (size_t)bh * S_ * HD_;

    // ---- stage Q into Ps, load Q fragments ----
#pragma unroll
    for (int p = 0; p < 8; p++) {
        int id = tid + p * 256;
        int r  = id >> 4;
        int c4 = (id & 15) << 2;
        *(float4*)&Ps[r * LDS_ + c4] = *(const float4*)(Qp + (size_t)(q0 + r) * HD_ + c4);
    }
    __syncthreads();

    uint32_t qa[8][4];
    {
        const float* base = Ps + (warp * 16) * LDS_;
#pragma unroll
        for (int kc = 0; kc < 8; kc++) {
            qa[kc][0] = __float_as_uint(base[(g)     * LDS_ + kc * 8 + c]);
            qa[kc][1] = __float_as_uint(base[(g + 8) * LDS_ + kc * 8 + c]);
            qa[kc][2] = __float_as_uint(base[(g)     * LDS_ + kc * 8 + c + 4]);
            qa[kc][3] = __float_as_uint(base[(g + 8) * LDS_ + kc * 8 + c + 4]);
        }
    }
    __syncthreads();    // Ps free for P reuse

    float o[8][4];
#pragma unroll
    for (int nt = 0; nt < 8; nt++)
#pragma unroll
        for (int e = 0; e < 4; e++) o[nt][e] = 0.f;
    float mrow[2] = {-1e30f, -1e30f};
    float lrow[2] = {0.f, 0.f};

    auto issue_kv = [&](int kt, int buf) {
        const float* Kg = Kp + (size_t)kt * 64 * HD_;
        const float* Vg = Vp + (size_t)kt * 64 * HD_;
        float* Kd = KsB + buf * KV_TILE_F;
        float* Vd = VsB + buf * KV_TILE_F;
#pragma unroll
        for (int p = 0; p < 4; p++) {
            int id = tid + p * 256;
            int r  = id >> 4;
            int c4 = (id & 15) << 2;
            cpa16(saddr(&Kd[r * LDS_ + c4]), Kg + r * HD_ + c4);
            cpa16(saddr(&Vd[r * LDS_ + c4]), Vg + r * HD_ + c4);
        }
    };

    issue_kv(0, 0);
    CP_COMMIT();

    for (int kt = 0; kt < NT_; kt++) {
        if (kt + 1 < NT_) {
            issue_kv(kt + 1, (kt + 1) & 1);
            CP_COMMIT();
            CP_WAIT1();
        } else {
            CP_WAIT0();
        }
        __syncthreads();

        const float* Ks = KsB + (kt & 1) * KV_TILE_F;
        const float* Vs = VsB + (kt & 1) * KV_TILE_F;

        // ---- S = Q @ K^T ----
        float s[8][4];
#pragma unroll
        for (int nt = 0; nt < 8; nt++)
#pragma unroll
            for (int e = 0; e < 4; e++) s[nt][e] = 0.f;

#pragma unroll
        for (int kc = 0; kc < 8; kc++) {
#pragma unroll
            for (int nt = 0; nt < 8; nt++) {
                uint32_t b0 = __float_as_uint(Ks[(nt * 8 + g) * LDS_ + kc * 8 + c]);
                uint32_t b1 = __float_as_uint(Ks[(nt * 8 + g) * LDS_ + kc * 8 + c + 4]);
                mma_tf32(s[nt], qa[kc], b0, b1);
            }
        }

        // ---- scale + online softmax in registers ----
#pragma unroll
        for (int nt = 0; nt < 8; nt++)
#pragma unroll
            for (int e = 0; e < 4; e++) s[nt][e] *= 0.125f;

#pragma unroll
        for (int h = 0; h < 2; h++) {
            float tm = -1e30f;
#pragma unroll
            for (int nt = 0; nt < 8; nt++)
                tm = fmaxf(tm, fmaxf(s[nt][2 * h], s[nt][2 * h + 1]));
            tm = fmaxf(tm, __shfl_xor_sync(0xffffffffu, tm, 1));
            tm = fmaxf(tm, __shfl_xor_sync(0xffffffffu, tm, 2));
            float mn   = fmaxf(mrow[h], tm);
            float corr = __expf(mrow[h] - mn);
            mrow[h] = mn;
            float ps = 0.f;
#pragma unroll
            for (int nt = 0; nt < 8; nt++) {
                float p0 = tf32r(__expf(s[nt][2 * h] - mn));
                float p1 = tf32r(__expf(s[nt][2 * h + 1] - mn));
                s[nt][2 * h] = p0; s[nt][2 * h + 1] = p1;
                ps += p0 + p1;
            }
            ps += __shfl_xor_sync(0xffffffffu, ps, 1);
            ps += __shfl_xor_sync(0xffffffffu, ps, 2);
            lrow[h] = lrow[h] * corr + ps;
#pragma unroll
            for (int nt = 0; nt < 8; nt++) {
                o[nt][2 * h]     *= corr;
                o[nt][2 * h + 1] *= corr;
            }
        }

        // ---- store P (warp-private rows) ----
        float* Pw = Ps + (warp * 16) * LDS_;
        __syncwarp();
#pragma unroll
        for (int nt = 0; nt < 8; nt++) {
            *(float2*)&Pw[(g)     * LDS_ + nt * 8 + 2 * c] = make_float2(s[nt][0], s[nt][1]);
            *(float2*)&Pw[(g + 8) * LDS_ + nt * 8 + 2 * c] = make_float2(s[nt][2], s[nt][3]);
        }
        __syncwarp();

        // ---- O += P @ V ----
#pragma unroll
        for (int kc = 0; kc < 8; kc++) {
            uint32_t pa[4];
            pa[0] = __float_as_uint(Pw[(g)     * LDS_ + kc * 8 + c]);
            pa[1] = __float_as_uint(Pw[(g + 8) * LDS_ + kc * 8 + c]);
            pa[2] = __float_as_uint(Pw[(g)     * LDS_ + kc * 8 + c + 4]);
            pa[3] = __float_as_uint(Pw[(g + 8) * LDS_ + kc * 8 + c + 4]);
#pragma unroll
            for (int nt = 0; nt < 8; nt++) {
                uint32_t b0 = __float_as_uint(Vs[(kc * 8 + c)     * LDS_ + nt * 8 + g]);
                uint32_t b1 = __float_as_uint(Vs[(kc * 8 + c + 4) * LDS_ + nt * 8 + g]);
                mma_tf32(o[nt], pa, b0, b1);
            }
        }
        __syncthreads();    // all done with this buffer before next overwrite
    }

    // ---- normalize + write g_attn (rounded for out-proj) ----
    const int b = bh >> 4;
    const int h = bh & 15;
    const float inv0 = 1.f / lrow[0];
    const float inv1 = 1.f / lrow[1];
    const int r0 = q0 + warp * 16 + g;
    const size_t base0 = ((size_t)(b * S_ + r0))     * D_ + h * 64;
    const size_t base1 = ((size_t)(b * S_ + r0 + 8)) * D_ + h * 64;
#pragma unroll
    for (int nt = 0; nt < 8; nt++) {
        int col = nt * 8 + 2 * c;
        *(float2*)(g_attn + base0 + col) =
            make_float2(tf32r(o[nt][0] * inv0), tf32r(o[nt][1] * inv0));
        *(float2*)(g_attn + base1 + col) =
            make_float2(tf32r(o[nt][2] * inv1), tf32r(o[nt][3] * inv1));
    }
}

// ---------------------------------------------------------------------------
extern "C" void kernel_launch(void* const* d_in, const int* in_sizes, int n_in,
                              void* d_out, int out_size)
{
    const float* x     = (const float*)d_in[0];
    const float* w_qkv = (const float*)d_in[1];
    const float* b_qkv = (const float*)d_in[2];
    const float* w_out = (const float*)d_in[3];
    const float* b_out = (const float*)d_in[4];
    float* out = (float*)d_out;

    static bool attr_set = false;
    if (!attr_set) {
        cudaFuncSetAttribute(attn_mma, cudaFuncAttributeMaxDynamicSharedMemorySize,
                             (4 * KV_TILE_F + 128 * LDS_) * 4);
        attr_set = true;
    }

    // 0) round inputs to tf32 scratch
    round_sel<<<1024, 256>>>(x,     0, (M_ * D_) / 4);
    round_sel<<<1024, 256>>>(w_qkv, 1, (D_ * 3 * D_) / 4);
    round_sel<<<1024, 256>>>(w_out, 2, (D_ * D_) / 4);

    // 1) QKV projection -> q/k/v (rounded)
    {
        dim3 grid((3 * D_) / 128, M_ / 128);
        gemm_tc<1><<<grid, 256>>>(b_qkv, nullptr, M_, 3 * D_, D_);
    }
    // 2) flash attention -> g_attn (rounded)
    {
        dim3 grid(S_ / 128, B_ * H_);
        attn_mma<<<grid, 256, (4 * KV_TILE_F + 128 * LDS_) * 4>>>();
    }
    // 3) output projection -> out (fp32)
    {
        dim3 grid(D_ / 128, M_ / 128);
        gemm_tc<2><<<grid, 256>>>(b_out, out, M_, D_, D_);
    }
}

// round 6
// speedup vs baseline: 6.9379x; 2.9918x over previous
#include <cuda_runtime.h>
#include <cuda_fp16.h>
#include <math.h>
#include <stdint.h>

#define B_  4
#define S_  2048
#define D_  1024
#define H_  16
#define HD_ 64
#define M_  (B_ * S_)
#define NT_ (S_ / 64)

// ---------------------------------------------------------------------------
// Scratch (__device__ globals; allocation-free rule). All fp16.
// ---------------------------------------------------------------------------
__device__ __half g_qh[(size_t)B_ * H_ * S_ * HD_];     // [b][h][s][hd]
__device__ __half g_kh[(size_t)B_ * H_ * S_ * HD_];     // [b][h][s][hd]
__device__ __half g_vth[(size_t)B_ * H_ * HD_ * S_];    // [b][h][hd][s]  (transposed)
__device__ __half g_attnh[(size_t)M_ * D_];             // [b*s][h*hd]
__device__ __half g_xh[(size_t)M_ * D_];                // x in fp16
__device__ __half g_wqkvh[(size_t)3 * D_ * D_];         // w_qkv^T [3D][D]
__device__ __half g_wouth[(size_t)D_ * D_];             // w_out^T [D][D]

// ---------------------------------------------------------------------------
// helpers
// ---------------------------------------------------------------------------
__device__ __forceinline__ uint32_t saddr(const void* p)
{
    return (uint32_t)__cvta_generic_to_shared(p);
}
__device__ __forceinline__ void cpa16(uint32_t dst, const void* src)
{
    asm volatile("cp.async.cg.shared.global [%0], [%1], 16;\n" :: "r"(dst), "l"(src));
}
#define CP_COMMIT() asm volatile("cp.async.commit_group;\n")
#define CP_WAIT1()  asm volatile("cp.async.wait_group 1;\n")
#define CP_WAIT0()  asm volatile("cp.async.wait_group 0;\n")

__device__ __forceinline__ void mma_f16(float* c, const uint32_t* a,
                                        uint32_t b0, uint32_t b1)
{
    asm volatile(
        "mma.sync.aligned.m16n8k16.row.col.f32.f16.f16.f32 "
        "{%0,%1,%2,%3}, {%4,%5,%6,%7}, {%8,%9}, {%0,%1,%2,%3};"
        : "+f"(c[0]), "+f"(c[1]), "+f"(c[2]), "+f"(c[3])
        : "r"(a[0]), "r"(a[1]), "r"(a[2]), "r"(a[3]), "r"(b0), "r"(b1));
}

__device__ __forceinline__ uint32_t packh2(float lo, float hi)
{
    __half2 h = __floats2half2_rn(lo, hi);
    return *(uint32_t*)&h;
}

// ---------------------------------------------------------------------------
// pre-pass: x -> fp16; weights -> transposed fp16 [N][K]
// ---------------------------------------------------------------------------
__global__ void conv_x(const float* __restrict__ src, int n4)
{
    for (int i = blockIdx.x * blockDim.x + threadIdx.x; i < n4;
         i += gridDim.x * blockDim.x) {
        float4 v = ((const float4*)src)[i];
        uint2 o;
        o.x = packh2(v.x, v.y);
        o.y = packh2(v.z, v.w);
        ((uint2*)g_xh)[i] = o;
    }
}

__global__ void transpose_conv(const float* __restrict__ src, int which,
                               int K, int N)   // src [K][N] f32 -> dst [N][K] f16
{
    __shared__ float t[32][33];
    __half* dst = (which == 1) ? g_wqkvh : g_wouth;
    const int nx = blockIdx.x * 32, ky = blockIdx.y * 32;
    const int tx = threadIdx.x, ty = threadIdx.y;
#pragma unroll
    for (int j = 0; j < 32; j += 8)
        t[ty + j][tx] = src[(size_t)(ky + ty + j) * N + nx + tx];
    __syncthreads();
#pragma unroll
    for (int j = 0; j < 32; j += 8)
        dst[(size_t)(nx + ty + j) * K + ky + tx] = __float2half(t[tx][ty + j]);
}

// ---------------------------------------------------------------------------
// fp16 mma GEMM: C[M,N] = A[M,K] @ Bt[N,K]^T + bias
// 128x128 block, BK=32, 256 threads (8 warps, 2m x 4n), warp 64x32.
//   EPI=1 : A=g_xh,   Bt=g_wqkvh -> scatter fp16 to g_qh/g_kh/g_vth
//   EPI=2 : A=g_attnh,Bt=g_wouth -> C fp32
// smem stride 40 halves: all fragment LDS.32 conflict-free.
// ---------------------------------------------------------------------------
#define ASTR 40

template <int EPI>
__global__ __launch_bounds__(256, 2)
void gemm_h(const float* __restrict__ bias, float* __restrict__ C,
            int Mn, int Nn, int Kn)
{
    __shared__ __half sA[2][128][ASTR];
    __shared__ __half sB[2][128][ASTR];

    const __half* A  = (EPI == 1) ? g_xh : g_attnh;
    const __half* Bt = (EPI == 1) ? g_wqkvh : g_wouth;

    const int tid  = threadIdx.x;
    const int warp = tid >> 5;
    const int lane = tid & 31;
    const int wm   = warp >> 2;
    const int wn   = warp & 3;
    const int g    = lane >> 2;
    const int c    = lane & 3;
    const int bm   = blockIdx.y * 128;
    const int bn   = blockIdx.x * 128;

    float acc[4][4][4];
#pragma unroll
    for (int mi = 0; mi < 4; mi++)
#pragma unroll
        for (int ni = 0; ni < 4; ni++)
#pragma unroll
            for (int e = 0; e < 4; e++) acc[mi][ni][e] = 0.f;

    auto load_chunk = [&](int kc, int buf) {
#pragma unroll
        for (int p = 0; p < 2; p++) {
            int id = tid + p * 256;
            int r  = id >> 2;
            int ch = id & 3;
            cpa16(saddr(&sA[buf][r][ch * 8]), A  + (size_t)(bm + r) * Kn + kc * 32 + ch * 8);
            cpa16(saddr(&sB[buf][r][ch * 8]), Bt + (size_t)(bn + r) * Kn + kc * 32 + ch * 8);
        }
    };

    const int NCH = Kn / 32;
    load_chunk(0, 0);
    CP_COMMIT();

    for (int it = 0; it < NCH; it++) {
        if (it + 1 < NCH) {
            load_chunk(it + 1, (it + 1) & 1);
            CP_COMMIT();
            CP_WAIT1();
        } else {
            CP_WAIT0();
        }
        __syncthreads();
        const int buf = it & 1;

#pragma unroll
        for (int kk = 0; kk < 2; kk++) {
            uint32_t af[4][4];
            uint32_t bf[4][2];
#pragma unroll
            for (int mi = 0; mi < 4; mi++) {
                const int r = wm * 64 + mi * 16;
                af[mi][0] = *(const uint32_t*)&sA[buf][r + g]    [kk * 16 + 2 * c];
                af[mi][1] = *(const uint32_t*)&sA[buf][r + 8 + g][kk * 16 + 2 * c];
                af[mi][2] = *(const uint32_t*)&sA[buf][r + g]    [kk * 16 + 2 * c + 8];
                af[mi][3] = *(const uint32_t*)&sA[buf][r + 8 + g][kk * 16 + 2 * c + 8];
            }
#pragma unroll
            for (int ni = 0; ni < 4; ni++) {
                const int r = wn * 32 + ni * 8 + g;
                bf[ni][0] = *(const uint32_t*)&sB[buf][r][kk * 16 + 2 * c];
                bf[ni][1] = *(const uint32_t*)&sB[buf][r][kk * 16 + 2 * c + 8];
            }
#pragma unroll
            for (int mi = 0; mi < 4; mi++)
#pragma unroll
                for (int ni = 0; ni < 4; ni++)
                    mma_f16(acc[mi][ni], af[mi], bf[ni][0], bf[ni][1]);
        }
        __syncthreads();
    }

    // ---- epilogue ----
#pragma unroll
    for (int mi = 0; mi < 4; mi++) {
        const int r0 = bm + wm * 64 + mi * 16 + g;
        const int r1 = r0 + 8;
#pragma unroll
        for (int ni = 0; ni < 4; ni++) {
            const int col0 = bn + wn * 32 + ni * 8 + 2 * c;
            const float bv0 = __ldg(bias + col0);
            const float bv1 = __ldg(bias + col0 + 1);
            const float v00 = acc[mi][ni][0] + bv0;
            const float v01 = acc[mi][ni][1] + bv1;
            const float v10 = acc[mi][ni][2] + bv0;
            const float v11 = acc[mi][ni][3] + bv1;
            if (EPI == 2) {
                *(float2*)(C + (size_t)r0 * Nn + col0) = make_float2(v00, v01);
                *(float2*)(C + (size_t)r1 * Nn + col0) = make_float2(v10, v11);
            } else {
                const int which = col0 >> 10;
                const int d0 = col0 & 1023;
                const int h  = d0 >> 6;
                const int hd = d0 & 63;
                const int b  = r0 >> 11;
                const int s0 = r0 & 2047;
                const int s1 = r1 & 2047;
                if (which < 2) {
                    __half* dst = which ? g_kh : g_qh;
                    const size_t base = (((size_t)b * H_ + h) * S_);
                    *(uint32_t*)(dst + (base + s0) * HD_ + hd) = packh2(v00, v01);
                    *(uint32_t*)(dst + (base + s1) * HD_ + hd) = packh2(v10, v11);
                } else {
                    const size_t base = (((size_t)b * H_ + h) * HD_);
                    g_vth[(base + hd)     * S_ + s0] = __float2half(v00);
                    g_vth[(base + hd + 1) * S_ + s0] = __float2half(v01);
                    g_vth[(base + hd)     * S_ + s1] = __float2half(v10);
                    g_vth[(base + hd + 1) * S_ + s1] = __float2half(v11);
                }
            }
        }
    }
}

// ---------------------------------------------------------------------------
// Flash attention, fp16 m16n8k16. Q tile 128, KV tile 64, HD 64.
// 8 warps; warp owns q rows [warp*16, +16). O in registers; P never leaves
// registers (S accum fragment == P a-fragment). V pre-transposed in gmem.
// ---------------------------------------------------------------------------
#define KSTR 72

__global__ __launch_bounds__(256, 2)
void attn_h()
{
    __shared__ __half sK[2][64][KSTR];
    __shared__ __half sV[2][64][KSTR];

    const int tid  = threadIdx.x;
    const int warp = tid >> 5;
    const int lane = tid & 31;
    const int g    = lane >> 2;
    const int c    = lane & 3;
    const int bh   = blockIdx.y;
    const int q0   = blockIdx.x * 128;

    const __half* Kp  = g_kh  + (size_t)bh * S_ * HD_;
    const __half* Vtp = g_vth + (size_t)bh * HD_ * S_;

    // ---- Q fragments straight from gmem ----
    uint32_t qa[4][4];
    {
        const int r0 = q0 + warp * 16 + g;
        const uint32_t* Q0 = (const uint32_t*)(g_qh + ((size_t)bh * S_ + r0) * HD_) + c;
        const uint32_t* Q1 = (const uint32_t*)(g_qh + ((size_t)bh * S_ + r0 + 8) * HD_) + c;
#pragma unroll
        for (int kk = 0; kk < 4; kk++) {
            qa[kk][0] = Q0[kk * 8];
            qa[kk][1] = Q1[kk * 8];
            qa[kk][2] = Q0[kk * 8 + 4];
            qa[kk][3] = Q1[kk * 8 + 4];
        }
    }

    float o[8][4];
#pragma unroll
    for (int nt = 0; nt < 8; nt++)
#pragma unroll
        for (int e = 0; e < 4; e++) o[nt][e] = 0.f;
    float mrow[2] = {-1e30f, -1e30f};
    float lrow[2] = {0.f, 0.f};

    auto issue_kv = [&](int kt, int buf) {
#pragma unroll
        for (int p = 0; p < 2; p++) {
            int id = tid + p * 256;
            int r  = id >> 3;
            int ch = id & 7;
            cpa16(saddr(&sK[buf][r][ch * 8]), Kp + (size_t)(kt * 64 + r) * HD_ + ch * 8);
            cpa16(saddr(&sV[buf][r][ch * 8]), Vtp + (size_t)r * S_ + kt * 64 + ch * 8);
        }
    };

    issue_kv(0, 0);
    CP_COMMIT();

    for (int kt = 0; kt < NT_; kt++) {
        if (kt + 1 < NT_) {
            issue_kv(kt + 1, (kt + 1) & 1);
            CP_COMMIT();
            CP_WAIT1();
        } else {
            CP_WAIT0();
        }
        __syncthreads();
        const int buf = kt & 1;

        // ---- S = Q @ K^T ----
        float s[8][4];
#pragma unroll
        for (int nt = 0; nt < 8; nt++)
#pragma unroll
            for (int e = 0; e < 4; e++) s[nt][e] = 0.f;

#pragma unroll
        for (int kk = 0; kk < 4; kk++) {
#pragma unroll
            for (int nt = 0; nt < 8; nt++) {
                uint32_t b0 = *(const uint32_t*)&sK[buf][nt * 8 + g][kk * 16 + 2 * c];
                uint32_t b1 = *(const uint32_t*)&sK[buf][nt * 8 + g][kk * 16 + 2 * c + 8];
                mma_f16(s[nt], qa[kk], b0, b1);
            }
        }

        // ---- online softmax (fp32 registers) ----
#pragma unroll
        for (int nt = 0; nt < 8; nt++)
#pragma unroll
            for (int e = 0; e < 4; e++) s[nt][e] *= 0.125f;

#pragma unroll
        for (int h = 0; h < 2; h++) {
            float tm = -1e30f;
#pragma unroll
            for (int nt = 0; nt < 8; nt++)
                tm = fmaxf(tm, fmaxf(s[nt][2 * h], s[nt][2 * h + 1]));
            tm = fmaxf(tm, __shfl_xor_sync(0xffffffffu, tm, 1));
            tm = fmaxf(tm, __shfl_xor_sync(0xffffffffu, tm, 2));
            const float mn   = fmaxf(mrow[h], tm);
            const float corr = __expf(mrow[h] - mn);
            mrow[h] = mn;
            float ps = 0.f;
#pragma unroll
            for (int nt = 0; nt < 8; nt++) {
                float p0 = __expf(s[nt][2 * h] - mn);
                float p1 = __expf(s[nt][2 * h + 1] - mn);
                s[nt][2 * h] = p0; s[nt][2 * h + 1] = p1;
                ps += p0 + p1;
            }
            ps += __shfl_xor_sync(0xffffffffu, ps, 1);
            ps += __shfl_xor_sync(0xffffffffu, ps, 2);
            lrow[h] = lrow[h] * corr + ps;
#pragma unroll
            for (int nt = 0; nt < 8; nt++) {
                o[nt][2 * h]     *= corr;
                o[nt][2 * h + 1] *= corr;
            }
        }

        // ---- P a-fragments straight from S accumulators ----
        uint32_t pa[4][4];
#pragma unroll
        for (int kk = 0; kk < 4; kk++) {
            pa[kk][0] = packh2(s[2 * kk][0],     s[2 * kk][1]);
            pa[kk][1] = packh2(s[2 * kk][2],     s[2 * kk][3]);
            pa[kk][2] = packh2(s[2 * kk + 1][0], s[2 * kk + 1][1]);
            pa[kk][3] = packh2(s[2 * kk + 1][2], s[2 * kk + 1][3]);
        }

        // ---- O += P @ V  (V transposed: b-frag is one contiguous u32) ----
#pragma unroll
        for (int kk = 0; kk < 4; kk++) {
#pragma unroll
            for (int nt = 0; nt < 8; nt++) {
                uint32_t b0 = *(const uint32_t*)&sV[buf][nt * 8 + g][kk * 16 + 2 * c];
                uint32_t b1 = *(const uint32_t*)&sV[buf][nt * 8 + g][kk * 16 + 2 * c + 8];
                mma_f16(o[nt], pa[kk], b0, b1);
            }
        }
        __syncthreads();
    }

    // ---- normalize + write g_attnh ----
    const int b = bh >> 4;
    const int h = bh & 15;
    const float inv0 = 1.f / lrow[0];
    const float inv1 = 1.f / lrow[1];
    const int r0 = q0 + warp * 16 + g;
    __half* d0 = g_attnh + ((size_t)(b * S_ + r0))     * D_ + h * 64;
    __half* d1 = g_attnh + ((size_t)(b * S_ + r0 + 8)) * D_ + h * 64;
#pragma unroll
    for (int nt = 0; nt < 8; nt++) {
        const int col = nt * 8 + 2 * c;
        *(uint32_t*)(d0 + col) = packh2(o[nt][0] * inv0, o[nt][1] * inv0);
        *(uint32_t*)(d1 + col) = packh2(o[nt][2] * inv1, o[nt][3] * inv1);
    }
}

// ---------------------------------------------------------------------------
extern "C" void kernel_launch(void* const* d_in, const int* in_sizes, int n_in,
                              void* d_out, int out_size)
{
    const float* x     = (const float*)d_in[0];
    const float* w_qkv = (const float*)d_in[1];
    const float* b_qkv = (const float*)d_in[2];
    const float* w_out = (const float*)d_in[3];
    const float* b_out = (const float*)d_in[4];
    float* out = (float*)d_out;

    // 0) pre-pass: convert x, transpose+convert weights
    conv_x<<<512, 256>>>(x, (M_ * D_) / 4);
    {
        dim3 blk(32, 8);
        transpose_conv<<<dim3((3 * D_) / 32, D_ / 32), blk>>>(w_qkv, 1, D_, 3 * D_);
        transpose_conv<<<dim3(D_ / 32, D_ / 32), blk>>>(w_out, 2, D_, D_);
    }
    // 1) QKV projection -> q/k (fp16) + v transposed (fp16)
    {
        dim3 grid((3 * D_) / 128, M_ / 128);   // 24 x 64
        gemm_h<1><<<grid, 256>>>(b_qkv, nullptr, M_, 3 * D_, D_);
    }
    // 2) flash attention -> g_attnh (fp16)
    {
        dim3 grid(S_ / 128, B_ * H_);          // 16 x 64
        attn_h<<<grid, 256>>>();
    }
    // 3) output projection -> out (fp32)
    {
        dim3 grid(D_ / 128, M_ / 128);         // 8 x 64
        gemm_h<2><<<grid, 256>>>(b_out, out, M_, D_, D_);
    }
}

// round 7
// speedup vs baseline: 7.5031x; 1.0815x over previous
#include <cuda_runtime.h>
#include <cuda_fp16.h>
#include <math.h>
#include <stdint.h>

#define B_  4
#define S_  2048
#define D_  1024
#define H_  16
#define HD_ 64
#define M_  (B_ * S_)
#define NT_ (S_ / 64)

// ---------------------------------------------------------------------------
// Scratch (__device__ globals; allocation-free rule). All fp16.
// ---------------------------------------------------------------------------
__device__ __half g_qh[(size_t)B_ * H_ * S_ * HD_];     // [b][h][s][hd]
__device__ __half g_kh[(size_t)B_ * H_ * S_ * HD_];     // [b][h][s][hd]
__device__ __half g_vth[(size_t)B_ * H_ * HD_ * S_];    // [b][h][hd][s]
__device__ __half g_attnh[(size_t)M_ * D_];             // [b*s][h*hd]
__device__ __half g_xh[(size_t)M_ * D_];
__device__ __half g_wqkvh[(size_t)3 * D_ * D_];         // w_qkv^T [3D][D]
__device__ __half g_wouth[(size_t)D_ * D_];             // w_out^T [D][D]

// ---------------------------------------------------------------------------
// helpers
// ---------------------------------------------------------------------------
__device__ __forceinline__ uint32_t saddr(const void* p)
{
    return (uint32_t)__cvta_generic_to_shared(p);
}
__device__ __forceinline__ void cpa16(uint32_t dst, const void* src)
{
    asm volatile("cp.async.cg.shared.global [%0], [%1], 16;\n" :: "r"(dst), "l"(src));
}
#define CP_COMMIT() asm volatile("cp.async.commit_group;\n")
#define CP_WAIT1()  asm volatile("cp.async.wait_group 1;\n")
#define CP_WAIT0()  asm volatile("cp.async.wait_group 0;\n")

__device__ __forceinline__ void ldsm4(uint32_t* r, uint32_t addr)
{
    asm volatile("ldmatrix.sync.aligned.m8n8.x4.shared.b16 {%0,%1,%2,%3}, [%4];"
                 : "=r"(r[0]), "=r"(r[1]), "=r"(r[2]), "=r"(r[3]) : "r"(addr));
}

__device__ __forceinline__ void mma_f16(float* c, const uint32_t* a,
                                        uint32_t b0, uint32_t b1)
{
    asm volatile(
        "mma.sync.aligned.m16n8k16.row.col.f32.f16.f16.f32 "
        "{%0,%1,%2,%3}, {%4,%5,%6,%7}, {%8,%9}, {%0,%1,%2,%3};"
        : "+f"(c[0]), "+f"(c[1]), "+f"(c[2]), "+f"(c[3])
        : "r"(a[0]), "r"(a[1]), "r"(a[2]), "r"(a[3]), "r"(b0), "r"(b1));
}

__device__ __forceinline__ uint32_t packh2(float lo, float hi)
{
    __half2 h = __floats2half2_rn(lo, hi);
    return *(uint32_t*)&h;
}

// ---------------------------------------------------------------------------
// pre-pass: x -> fp16; weights -> transposed fp16 [N][K]
// ---------------------------------------------------------------------------
__global__ void conv_x(const float* __restrict__ src, int n4)
{
    for (int i = blockIdx.x * blockDim.x + threadIdx.x; i < n4;
         i += gridDim.x * blockDim.x) {
        float4 v = ((const float4*)src)[i];
        uint2 o;
        o.x = packh2(v.x, v.y);
        o.y = packh2(v.z, v.w);
        ((uint2*)g_xh)[i] = o;
    }
}

__global__ void transpose_conv(const float* __restrict__ src, int which,
                               int K, int N)
{
    __shared__ float t[32][33];
    __half* dst = (which == 1) ? g_wqkvh : g_wouth;
    const int nx = blockIdx.x * 32, ky = blockIdx.y * 32;
    const int tx = threadIdx.x, ty = threadIdx.y;
#pragma unroll
    for (int j = 0; j < 32; j += 8)
        t[ty + j][tx] = src[(size_t)(ky + ty + j) * N + nx + tx];
    __syncthreads();
#pragma unroll
    for (int j = 0; j < 32; j += 8)
        dst[(size_t)(nx + ty + j) * K + ky + tx] = __float2half(t[tx][ty + j]);
}

// ---------------------------------------------------------------------------
// fp16 mma GEMM: C[M,N] = A[M,K] @ Bt[N,K]^T + bias
// 128x128 block, BK=32, 256 threads, warp 64x32. 3-stage cp.async.
// ldmatrix.x4 fragment loads. smem stride 40 halves (LDSM conflict-free).
// ---------------------------------------------------------------------------
#define ASTR 40
#define GSTG 3
#define GTILE (128 * ASTR)                       // halves per tile
#define GEMM_SMEM (2 * GSTG * GTILE * 2)         // bytes = 61440

template <int EPI>
__global__ __launch_bounds__(256, 2)
void gemm_h(const float* __restrict__ bias, float* __restrict__ C,
            int Mn, int Nn, int Kn)
{
    extern __shared__ __half gsm[];
    __half* sA = gsm;                            // [GSTG][128][ASTR]
    __half* sB = gsm + GSTG * GTILE;             // [GSTG][128][ASTR]

    const __half* A  = (EPI == 1) ? g_xh : g_attnh;
    const __half* Bt = (EPI == 1) ? g_wqkvh : g_wouth;

    const int tid  = threadIdx.x;
    const int warp = tid >> 5;
    const int lane = tid & 31;
    const int wm   = warp >> 2;
    const int wn   = warp & 3;
    const int g    = lane >> 2;
    const int c    = lane & 3;
    const int bm   = blockIdx.y * 128;
    const int bn   = blockIdx.x * 128;

    // ldmatrix lane->row/col mapping
    const int a_r = lane & 15;
    const int a_c = (lane >> 4) << 3;
    const int b_r = (lane & 7) + ((lane >> 4) << 3);
    const int b_c = ((lane >> 3) & 1) << 3;

    float acc[4][4][4];
#pragma unroll
    for (int mi = 0; mi < 4; mi++)
#pragma unroll
        for (int ni = 0; ni < 4; ni++)
#pragma unroll
            for (int e = 0; e < 4; e++) acc[mi][ni][e] = 0.f;

    auto load_chunk = [&](int kc, int buf) {
        __half* dA = sA + buf * GTILE;
        __half* dB = sB + buf * GTILE;
#pragma unroll
        for (int p = 0; p < 2; p++) {
            int id = tid + p * 256;
            int r  = id >> 2;
            int ch = id & 3;
            cpa16(saddr(dA + r * ASTR + ch * 8), A  + (size_t)(bm + r) * Kn + kc * 32 + ch * 8);
            cpa16(saddr(dB + r * ASTR + ch * 8), Bt + (size_t)(bn + r) * Kn + kc * 32 + ch * 8);
        }
    };

    const int NCH = Kn / 32;
    load_chunk(0, 0); CP_COMMIT();
    load_chunk(1, 1); CP_COMMIT();

    int buf = 0;
    for (int it = 0; it < NCH; it++) {
        if (it + 1 < NCH) { CP_WAIT1(); } else { CP_WAIT0(); }
        __syncthreads();
        if (it + 2 < NCH) {
            int nb = buf + 2; if (nb >= GSTG) nb -= GSTG;
            load_chunk(it + 2, nb);
            CP_COMMIT();
        }

        const uint32_t aB = saddr(sA + buf * GTILE + (wm * 64 + a_r) * ASTR + a_c);
        const uint32_t bB = saddr(sB + buf * GTILE + (wn * 32 + b_r) * ASTR + b_c);
#pragma unroll
        for (int kk = 0; kk < 2; kk++) {
            uint32_t af[4][4];
            uint32_t bfr[8];
#pragma unroll
            for (int mi = 0; mi < 4; mi++)
                ldsm4(af[mi], aB + (mi * 16 * ASTR + kk * 16) * 2);
#pragma unroll
            for (int np = 0; np < 2; np++)
                ldsm4(bfr + np * 4, bB + (np * 16 * ASTR + kk * 16) * 2);
#pragma unroll
            for (int mi = 0; mi < 4; mi++)
#pragma unroll
                for (int ni = 0; ni < 4; ni++)
                    mma_f16(acc[mi][ni], af[mi], bfr[ni * 2], bfr[ni * 2 + 1]);
        }
        if (++buf == GSTG) buf = 0;
    }

    // ---- epilogue ----
#pragma unroll
    for (int mi = 0; mi < 4; mi++) {
        const int r0 = bm + wm * 64 + mi * 16 + g;
        const int r1 = r0 + 8;
#pragma unroll
        for (int ni = 0; ni < 4; ni++) {
            const int col0 = bn + wn * 32 + ni * 8 + 2 * c;
            const float bv0 = __ldg(bias + col0);
            const float bv1 = __ldg(bias + col0 + 1);
            const float v00 = acc[mi][ni][0] + bv0;
            const float v01 = acc[mi][ni][1] + bv1;
            const float v10 = acc[mi][ni][2] + bv0;
            const float v11 = acc[mi][ni][3] + bv1;
            if (EPI == 2) {
                *(float2*)(C + (size_t)r0 * Nn + col0) = make_float2(v00, v01);
                *(float2*)(C + (size_t)r1 * Nn + col0) = make_float2(v10, v11);
            } else {
                const int which = col0 >> 10;
                const int d0 = col0 & 1023;
                const int h  = d0 >> 6;
                const int hd = d0 & 63;
                const int b  = r0 >> 11;
                const int s0 = r0 & 2047;
                const int s1 = r1 & 2047;
                if (which < 2) {
                    __half* dst = which ? g_kh : g_qh;
                    const size_t base = (((size_t)b * H_ + h) * S_);
                    *(uint32_t*)(dst + (base + s0) * HD_ + hd) = packh2(v00, v01);
                    *(uint32_t*)(dst + (base + s1) * HD_ + hd) = packh2(v10, v11);
                } else {
                    const size_t base = (((size_t)b * H_ + h) * HD_);
                    g_vth[(base + hd)     * S_ + s0] = __float2half(v00);
                    g_vth[(base + hd + 1) * S_ + s0] = __float2half(v01);
                    g_vth[(base + hd)     * S_ + s1] = __float2half(v10);
                    g_vth[(base + hd + 1) * S_ + s1] = __float2half(v11);
                }
            }
        }
    }
}

// ---------------------------------------------------------------------------
// Flash attention, fp16 m16n8k16 + ldmatrix. Q tile 128, KV tile 64, HD 64.
// Single __syncthreads per kv tile; loads overlap compute (2-stage).
// ---------------------------------------------------------------------------
#define KSTR 72
#define KVTILE (64 * KSTR)

__global__ __launch_bounds__(256, 2)
void attn_h()
{
    __shared__ __half sK[2][64][KSTR];
    __shared__ __half sV[2][64][KSTR];

    const int tid  = threadIdx.x;
    const int warp = tid >> 5;
    const int lane = tid & 31;
    const int g    = lane >> 2;
    const int c    = lane & 3;
    const int bh   = blockIdx.y;
    const int q0   = blockIdx.x * 128;

    const __half* Kp  = g_kh  + (size_t)bh * S_ * HD_;
    const __half* Vtp = g_vth + (size_t)bh * HD_ * S_;

    const int b_r = (lane & 7) + ((lane >> 4) << 3);
    const int b_c = ((lane >> 3) & 1) << 3;

    // ---- Q fragments straight from gmem ----
    uint32_t qa[4][4];
    {
        const int r0 = q0 + warp * 16 + g;
        const uint32_t* Q0 = (const uint32_t*)(g_qh + ((size_t)bh * S_ + r0) * HD_) + c;
        const uint32_t* Q1 = (const uint32_t*)(g_qh + ((size_t)bh * S_ + r0 + 8) * HD_) + c;
#pragma unroll
        for (int kk = 0; kk < 4; kk++) {
            qa[kk][0] = Q0[kk * 8];
            qa[kk][1] = Q1[kk * 8];
            qa[kk][2] = Q0[kk * 8 + 4];
            qa[kk][3] = Q1[kk * 8 + 4];
        }
    }

    float o[8][4];
#pragma unroll
    for (int nt = 0; nt < 8; nt++)
#pragma unroll
        for (int e = 0; e < 4; e++) o[nt][e] = 0.f;
    float mrow[2] = {-1e30f, -1e30f};
    float lrow[2] = {0.f, 0.f};

    auto issue_kv = [&](int kt, int bufi) {
#pragma unroll
        for (int p = 0; p < 2; p++) {
            int id = tid + p * 256;
            int r  = id >> 3;
            int ch = id & 7;
            cpa16(saddr(&sK[bufi][r][ch * 8]), Kp  + (size_t)(kt * 64 + r) * HD_ + ch * 8);
            cpa16(saddr(&sV[bufi][r][ch * 8]), Vtp + (size_t)r * S_ + kt * 64 + ch * 8);
        }
    };

    issue_kv(0, 0);
    CP_COMMIT();

    for (int kt = 0; kt < NT_; kt++) {
        CP_WAIT0();
        __syncthreads();                  // buffer kt ready; all warps done with kt-1
        if (kt + 1 < NT_) {
            issue_kv(kt + 1, (kt + 1) & 1);
            CP_COMMIT();
        }
        const int bufi = kt & 1;
        const uint32_t kB = saddr(&sK[bufi][b_r][b_c]);
        const uint32_t vB = saddr(&sV[bufi][b_r][b_c]);

        // ---- S = Q @ K^T ----
        float s[8][4];
#pragma unroll
        for (int nt = 0; nt < 8; nt++)
#pragma unroll
            for (int e = 0; e < 4; e++) s[nt][e] = 0.f;

#pragma unroll
        for (int kk = 0; kk < 4; kk++) {
            uint32_t kb[16];
#pragma unroll
            for (int np = 0; np < 4; np++)
                ldsm4(kb + np * 4, kB + (np * 16 * KSTR + kk * 16) * 2);
#pragma unroll
            for (int nt = 0; nt < 8; nt++)
                mma_f16(s[nt], qa[kk], kb[nt * 2], kb[nt * 2 + 1]);
        }

        // ---- online softmax (fp32 registers) ----
#pragma unroll
        for (int nt = 0; nt < 8; nt++)
#pragma unroll
            for (int e = 0; e < 4; e++) s[nt][e] *= 0.125f;

#pragma unroll
        for (int h = 0; h < 2; h++) {
            float tm = -1e30f;
#pragma unroll
            for (int nt = 0; nt < 8; nt++)
                tm = fmaxf(tm, fmaxf(s[nt][2 * h], s[nt][2 * h + 1]));
            tm = fmaxf(tm, __shfl_xor_sync(0xffffffffu, tm, 1));
            tm = fmaxf(tm, __shfl_xor_sync(0xffffffffu, tm, 2));
            const float mn   = fmaxf(mrow[h], tm);
            const float corr = __expf(mrow[h] - mn);
            mrow[h] = mn;
            float ps = 0.f;
#pragma unroll
            for (int nt = 0; nt < 8; nt++) {
                float p0 = __expf(s[nt][2 * h] - mn);
                float p1 = __expf(s[nt][2 * h + 1] - mn);
                s[nt][2 * h] = p0; s[nt][2 * h + 1] = p1;
                ps += p0 + p1;
            }
            ps += __shfl_xor_sync(0xffffffffu, ps, 1);
            ps += __shfl_xor_sync(0xffffffffu, ps, 2);
            lrow[h] = lrow[h] * corr + ps;
#pragma unroll
            for (int nt = 0; nt < 8; nt++) {
                o[nt][2 * h]     *= corr;
                o[nt][2 * h + 1] *= corr;
            }
        }

        // ---- P a-fragments straight from S accumulators ----
        uint32_t pa[4][4];
#pragma unroll
        for (int kk = 0; kk < 4; kk++) {
            pa[kk][0] = packh2(s[2 * kk][0],     s[2 * kk][1]);
            pa[kk][1] = packh2(s[2 * kk][2],     s[2 * kk][3]);
            pa[kk][2] = packh2(s[2 * kk + 1][0], s[2 * kk + 1][1]);
            pa[kk][3] = packh2(s[2 * kk + 1][2], s[2 * kk + 1][3]);
        }

        // ---- O += P @ V ----
#pragma unroll
        for (int kk = 0; kk < 4; kk++) {
            uint32_t vb[16];
#pragma unroll
            for (int np = 0; np < 4; np++)
                ldsm4(vb + np * 4, vB + (np * 16 * KSTR + kk * 16) * 2);
#pragma unroll
            for (int nt = 0; nt < 8; nt++)
                mma_f16(o[nt], pa[kk], vb[nt * 2], vb[nt * 2 + 1]);
        }
    }

    // ---- normalize + write g_attnh ----
    const int b = bh >> 4;
    const int h = bh & 15;
    const float inv0 = 1.f / lrow[0];
    const float inv1 = 1.f / lrow[1];
    const int r0 = q0 + warp * 16 + g;
    __half* d0 = g_attnh + ((size_t)(b * S_ + r0))     * D_ + h * 64;
    __half* d1 = g_attnh + ((size_t)(b * S_ + r0 + 8)) * D_ + h * 64;
#pragma unroll
    for (int nt = 0; nt < 8; nt++) {
        const int col = nt * 8 + 2 * c;
        *(uint32_t*)(d0 + col) = packh2(o[nt][0] * inv0, o[nt][1] * inv0);
        *(uint32_t*)(d1 + col) = packh2(o[nt][2] * inv1, o[nt][3] * inv1);
    }
}

// ---------------------------------------------------------------------------
extern "C" void kernel_launch(void* const* d_in, const int* in_sizes, int n_in,
                              void* d_out, int out_size)
{
    const float* x     = (const float*)d_in[0];
    const float* w_qkv = (const float*)d_in[1];
    const float* b_qkv = (const float*)d_in[2];
    const float* w_out = (const float*)d_in[3];
    const float* b_out = (const float*)d_in[4];
    float* out = (float*)d_out;

    cudaFuncSetAttribute(gemm_h<1>, cudaFuncAttributeMaxDynamicSharedMemorySize, GEMM_SMEM);
    cudaFuncSetAttribute(gemm_h<2>, cudaFuncAttributeMaxDynamicSharedMemorySize, GEMM_SMEM);

    // 0) pre-pass
    conv_x<<<512, 256>>>(x, (M_ * D_) / 4);
    {
        dim3 blk(32, 8);
        transpose_conv<<<dim3((3 * D_) / 32, D_ / 32), blk>>>(w_qkv, 1, D_, 3 * D_);
        transpose_conv<<<dim3(D_ / 32, D_ / 32), blk>>>(w_out, 2, D_, D_);
    }
    // 1) QKV projection
    {
        dim3 grid((3 * D_) / 128, M_ / 128);
        gemm_h<1><<<grid, 256, GEMM_SMEM>>>(b_qkv, nullptr, M_, 3 * D_, D_);
    }
    // 2) flash attention
    {
        dim3 grid(S_ / 128, B_ * H_);
        attn_h<<<grid, 256>>>();
    }
    // 3) output projection
    {
        dim3 grid(D_ / 128, M_ / 128);
        gemm_h<2><<<grid, 256, GEMM_SMEM>>>(b_out, out, M_, D_, D_);
    }
}

// round 8
// speedup vs baseline: 8.3853x; 1.1176x over previous
#include <cuda_runtime.h>
#include <cuda_fp16.h>
#include <math.h>
#include <stdint.h>

#define B_  4
#define S_  2048
#define D_  1024
#define H_  16
#define HD_ 64
#define M_  (B_ * S_)
#define NT_ (S_ / 64)

// scale folded into Q: 1/sqrt(64) * log2(e)
#define QSC 0.18033688045f

// ---------------------------------------------------------------------------
// Scratch (__device__ globals; allocation-free rule). All fp16.
// ---------------------------------------------------------------------------
__device__ __half g_qh[(size_t)B_ * H_ * S_ * HD_];     // [b][h][s][hd], pre-scaled
__device__ __half g_kh[(size_t)B_ * H_ * S_ * HD_];     // [b][h][s][hd]
__device__ __half g_vth[(size_t)B_ * H_ * HD_ * S_];    // [b][h][hd][s]
__device__ __half g_attnh[(size_t)M_ * D_];             // [b*s][h*hd]
__device__ __half g_xh[(size_t)M_ * D_];
__device__ __half g_wqkvh[(size_t)3 * D_ * D_];         // w_qkv^T [3D][D]
__device__ __half g_wouth[(size_t)D_ * D_];             // w_out^T [D][D]

// ---------------------------------------------------------------------------
// helpers
// ---------------------------------------------------------------------------
__device__ __forceinline__ uint32_t saddr(const void* p)
{
    return (uint32_t)__cvta_generic_to_shared(p);
}
__device__ __forceinline__ void cpa16(uint32_t dst, const void* src)
{
    asm volatile("cp.async.cg.shared.global [%0], [%1], 16;\n" :: "r"(dst), "l"(src));
}
#define CP_COMMIT() asm volatile("cp.async.commit_group;\n")
#define CP_WAIT0()  asm volatile("cp.async.wait_group 0;\n")

__device__ __forceinline__ void ldsm4(uint32_t* r, uint32_t addr)
{
    asm volatile("ldmatrix.sync.aligned.m8n8.x4.shared.b16 {%0,%1,%2,%3}, [%4];"
                 : "=r"(r[0]), "=r"(r[1]), "=r"(r[2]), "=r"(r[3]) : "r"(addr));
}

__device__ __forceinline__ void mma_f16(float* c, const uint32_t* a,
                                        uint32_t b0, uint32_t b1)
{
    asm volatile(
        "mma.sync.aligned.m16n8k16.row.col.f32.f16.f16.f32 "
        "{%0,%1,%2,%3}, {%4,%5,%6,%7}, {%8,%9}, {%0,%1,%2,%3};"
        : "+f"(c[0]), "+f"(c[1]), "+f"(c[2]), "+f"(c[3])
        : "r"(a[0]), "r"(a[1]), "r"(a[2]), "r"(a[3]), "r"(b0), "r"(b1));
}

__device__ __forceinline__ uint32_t packh2(float lo, float hi)
{
    __half2 h = __floats2half2_rn(lo, hi);
    return *(uint32_t*)&h;
}
__device__ __forceinline__ float ex2f(float x)
{
    float y;
    asm("ex2.approx.f32 %0, %1;" : "=f"(y) : "f"(x));
    return y;
}
// p = ex2( pack(lo,hi) - m2 )  computed entirely in f16x2; returns fragment u32
__device__ __forceinline__ uint32_t h2exp2sub(float lo, float hi, uint32_t m2)
{
    uint32_t s2 = packh2(lo, hi);
    uint32_t d, r;
    asm("sub.f16x2 %0, %1, %2;" : "=r"(d) : "r"(s2), "r"(m2));
    asm("ex2.approx.f16x2 %0, %1;" : "=r"(r) : "r"(d));
    return r;
}

// ---------------------------------------------------------------------------
// pre-pass: x -> fp16; weights -> transposed fp16 [N][K]
// ---------------------------------------------------------------------------
__global__ void conv_x(const float* __restrict__ src, int n4)
{
    for (int i = blockIdx.x * blockDim.x + threadIdx.x; i < n4;
         i += gridDim.x * blockDim.x) {
        float4 v = ((const float4*)src)[i];
        uint2 o;
        o.x = packh2(v.x, v.y);
        o.y = packh2(v.z, v.w);
        ((uint2*)g_xh)[i] = o;
    }
}

__global__ void transpose_conv(const float* __restrict__ src, int which,
                               int K, int N)
{
    __shared__ float t[32][33];
    __half* dst = (which == 1) ? g_wqkvh : g_wouth;
    const int nx = blockIdx.x * 32, ky = blockIdx.y * 32;
    const int tx = threadIdx.x, ty = threadIdx.y;
#pragma unroll
    for (int j = 0; j < 32; j += 8)
        t[ty + j][tx] = src[(size_t)(ky + ty + j) * N + nx + tx];
    __syncthreads();
#pragma unroll
    for (int j = 0; j < 32; j += 8)
        dst[(size_t)(nx + ty + j) * K + ky + tx] = __float2half(t[tx][ty + j]);
}

// ---------------------------------------------------------------------------
// fp16 mma GEMM: C[M,N] = A[M,K] @ Bt[N,K]^T + bias
// 128x128 block, BK=64, 256 threads, warp 64x32. 2-stage cp.async,
// one barrier per K-chunk. smem stride 72 halves (LDSM conflict-free).
// ---------------------------------------------------------------------------
#define ASTR 72
#define GTILE (128 * ASTR)                       // halves per matrix per stage
#define GEMM_SMEM (2 * 2 * GTILE * 2)            // 73728 B

template <int EPI>
__global__ __launch_bounds__(256, 2)
void gemm_h(const float* __restrict__ bias, float* __restrict__ C,
            int Mn, int Nn, int Kn)
{
    extern __shared__ __half gsm[];
    __half* sA = gsm;                            // [2][128][ASTR]
    __half* sB = gsm + 2 * GTILE;                // [2][128][ASTR]

    const __half* A  = (EPI == 1) ? g_xh : g_attnh;
    const __half* Bt = (EPI == 1) ? g_wqkvh : g_wouth;

    const int tid  = threadIdx.x;
    const int warp = tid >> 5;
    const int lane = tid & 31;
    const int wm   = warp >> 2;
    const int wn   = warp & 3;
    const int g    = lane >> 2;
    const int c    = lane & 3;
    const int bm   = blockIdx.y * 128;
    const int bn   = blockIdx.x * 128;

    const int a_r = lane & 15;
    const int a_c = (lane >> 4) << 3;
    const int b_r = (lane & 7) + ((lane >> 4) << 3);
    const int b_c = ((lane >> 3) & 1) << 3;

    float acc[4][4][4];
#pragma unroll
    for (int mi = 0; mi < 4; mi++)
#pragma unroll
        for (int ni = 0; ni < 4; ni++)
#pragma unroll
            for (int e = 0; e < 4; e++) acc[mi][ni][e] = 0.f;

    auto load_chunk = [&](int kc, int buf) {
        __half* dA = sA + buf * GTILE;
        __half* dB = sB + buf * GTILE;
#pragma unroll
        for (int p = 0; p < 4; p++) {
            int id = tid + p * 256;              // 0..1023
            int r  = id >> 3;
            int ch = id & 7;
            cpa16(saddr(dA + r * ASTR + ch * 8), A  + (size_t)(bm + r) * Kn + kc * 64 + ch * 8);
            cpa16(saddr(dB + r * ASTR + ch * 8), Bt + (size_t)(bn + r) * Kn + kc * 64 + ch * 8);
        }
    };

    const int NCH = Kn / 64;
    load_chunk(0, 0);
    CP_COMMIT();

    for (int it = 0; it < NCH; it++) {
        CP_WAIT0();
        __syncthreads();                         // buffer it ready; all warps past it-1
        if (it + 1 < NCH) {
            load_chunk(it + 1, (it + 1) & 1);
            CP_COMMIT();
        }
        const int buf = it & 1;
        const uint32_t aB = saddr(sA + buf * GTILE + (wm * 64 + a_r) * ASTR + a_c);
        const uint32_t bB = saddr(sB + buf * GTILE + (wn * 32 + b_r) * ASTR + b_c);
#pragma unroll
        for (int kk = 0; kk < 4; kk++) {
            uint32_t af[4][4];
            uint32_t bfr[8];
#pragma unroll
            for (int mi = 0; mi < 4; mi++)
                ldsm4(af[mi], aB + (mi * 16 * ASTR + kk * 16) * 2);
#pragma unroll
            for (int np = 0; np < 2; np++)
                ldsm4(bfr + np * 4, bB + (np * 16 * ASTR + kk * 16) * 2);
#pragma unroll
            for (int mi = 0; mi < 4; mi++)
#pragma unroll
                for (int ni = 0; ni < 4; ni++)
                    mma_f16(acc[mi][ni], af[mi], bfr[ni * 2], bfr[ni * 2 + 1]);
        }
    }

    // ---- epilogue ----
#pragma unroll
    for (int mi = 0; mi < 4; mi++) {
        const int r0 = bm + wm * 64 + mi * 16 + g;
        const int r1 = r0 + 8;
#pragma unroll
        for (int ni = 0; ni < 4; ni++) {
            const int col0 = bn + wn * 32 + ni * 8 + 2 * c;
            const float bv0 = __ldg(bias + col0);
            const float bv1 = __ldg(bias + col0 + 1);
            float v00 = acc[mi][ni][0] + bv0;
            float v01 = acc[mi][ni][1] + bv1;
            float v10 = acc[mi][ni][2] + bv0;
            float v11 = acc[mi][ni][3] + bv1;
            if (EPI == 2) {
                *(float2*)(C + (size_t)r0 * Nn + col0) = make_float2(v00, v01);
                *(float2*)(C + (size_t)r1 * Nn + col0) = make_float2(v10, v11);
            } else {
                const int which = col0 >> 10;
                const int d0 = col0 & 1023;
                const int h  = d0 >> 6;
                const int hd = d0 & 63;
                const int b  = r0 >> 11;
                const int s0 = r0 & 2047;
                const int s1 = r1 & 2047;
                if (which == 0) {                // Q: fold softmax scale (log2 dom)
                    v00 *= QSC; v01 *= QSC; v10 *= QSC; v11 *= QSC;
                    const size_t base = (((size_t)b * H_ + h) * S_);
                    *(uint32_t*)(g_qh + (base + s0) * HD_ + hd) = packh2(v00, v01);
                    *(uint32_t*)(g_qh + (base + s1) * HD_ + hd) = packh2(v10, v11);
                } else if (which == 1) {
                    const size_t base = (((size_t)b * H_ + h) * S_);
                    *(uint32_t*)(g_kh + (base + s0) * HD_ + hd) = packh2(v00, v01);
                    *(uint32_t*)(g_kh + (base + s1) * HD_ + hd) = packh2(v10, v11);
                } else {
                    const size_t base = (((size_t)b * H_ + h) * HD_);
                    g_vth[(base + hd)     * S_ + s0] = __float2half(v00);
                    g_vth[(base + hd + 1) * S_ + s0] = __float2half(v01);
                    g_vth[(base + hd)     * S_ + s1] = __float2half(v10);
                    g_vth[(base + hd + 1) * S_ + s1] = __float2half(v11);
                }
            }
        }
    }
}

// ---------------------------------------------------------------------------
// Flash attention, fp16 m16n8k16 + ldmatrix, log2-domain softmax,
// fp16x2 exponentials, row-sum l via ones-operand MMA.
// Q tile 128, KV tile 64, HD 64; 8 warps.
// ---------------------------------------------------------------------------
#define KSTR 72
#define ONE2 0x3C003C00u

__global__ __launch_bounds__(256, 2)
void attn_h()
{
    __shared__ __half sK[2][64][KSTR];
    __shared__ __half sV[2][64][KSTR];

    const int tid  = threadIdx.x;
    const int warp = tid >> 5;
    const int lane = tid & 31;
    const int g    = lane >> 2;
    const int c    = lane & 3;
    const int bh   = blockIdx.y;
    const int q0   = blockIdx.x * 128;

    const __half* Kp  = g_kh  + (size_t)bh * S_ * HD_;
    const __half* Vtp = g_vth + (size_t)bh * HD_ * S_;

    const int b_r = (lane & 7) + ((lane >> 4) << 3);
    const int b_c = ((lane >> 3) & 1) << 3;

    // ---- Q fragments straight from gmem (pre-scaled by QSC) ----
    uint32_t qa[4][4];
    {
        const int r0 = q0 + warp * 16 + g;
        const uint32_t* Q0 = (const uint32_t*)(g_qh + ((size_t)bh * S_ + r0) * HD_) + c;
        const uint32_t* Q1 = (const uint32_t*)(g_qh + ((size_t)bh * S_ + r0 + 8) * HD_) + c;
#pragma unroll
        for (int kk = 0; kk < 4; kk++) {
            qa[kk][0] = Q0[kk * 8];
            qa[kk][1] = Q1[kk * 8];
            qa[kk][2] = Q0[kk * 8 + 4];
            qa[kk][3] = Q1[kk * 8 + 4];
        }
    }

    float o[8][4];
#pragma unroll
    for (int nt = 0; nt < 8; nt++)
#pragma unroll
        for (int e = 0; e < 4; e++) o[nt][e] = 0.f;
    float osum[4] = {0.f, 0.f, 0.f, 0.f};        // row sums of P (l), via ones-MMA
    float mrow[2] = {-1e30f, -1e30f};

    auto issue_kv = [&](int kt, int bufi) {
#pragma unroll
        for (int p = 0; p < 2; p++) {
            int id = tid + p * 256;
            int r  = id >> 3;
            int ch = id & 7;
            cpa16(saddr(&sK[bufi][r][ch * 8]), Kp  + (size_t)(kt * 64 + r) * HD_ + ch * 8);
            cpa16(saddr(&sV[bufi][r][ch * 8]), Vtp + (size_t)r * S_ + kt * 64 + ch * 8);
        }
    };

    issue_kv(0, 0);
    CP_COMMIT();

    for (int kt = 0; kt < NT_; kt++) {
        CP_WAIT0();
        __syncthreads();
        if (kt + 1 < NT_) {
            issue_kv(kt + 1, (kt + 1) & 1);
            CP_COMMIT();
        }
        const int bufi = kt & 1;
        const uint32_t kB = saddr(&sK[bufi][b_r][b_c]);
        const uint32_t vB = saddr(&sV[bufi][b_r][b_c]);

        // ---- S = Q @ K^T  (log2 units; scale pre-folded into Q) ----
        float s[8][4];
#pragma unroll
        for (int nt = 0; nt < 8; nt++)
#pragma unroll
            for (int e = 0; e < 4; e++) s[nt][e] = 0.f;

#pragma unroll
        for (int kk = 0; kk < 4; kk++) {
            uint32_t kb[16];
#pragma unroll
            for (int np = 0; np < 4; np++)
                ldsm4(kb + np * 4, kB + (np * 16 * KSTR + kk * 16) * 2);
#pragma unroll
            for (int nt = 0; nt < 8; nt++)
                mma_f16(s[nt], qa[kk], kb[nt * 2], kb[nt * 2 + 1]);
        }

        // ---- online softmax: max + rescale (fp32), exp in f16x2 ----
        float mn[2], corr[2];
#pragma unroll
        for (int h = 0; h < 2; h++) {
            float tm = -1e30f;
#pragma unroll
            for (int nt = 0; nt < 8; nt++)
                tm = fmaxf(tm, fmaxf(s[nt][2 * h], s[nt][2 * h + 1]));
            tm = fmaxf(tm, __shfl_xor_sync(0xffffffffu, tm, 1));
            tm = fmaxf(tm, __shfl_xor_sync(0xffffffffu, tm, 2));
            mn[h]   = fmaxf(mrow[h], tm);
            corr[h] = ex2f(mrow[h] - mn[h]);
            mrow[h] = mn[h];
        }
#pragma unroll
        for (int nt = 0; nt < 8; nt++) {
            o[nt][0] *= corr[0]; o[nt][1] *= corr[0];
            o[nt][2] *= corr[1]; o[nt][3] *= corr[1];
        }
        osum[0] *= corr[0]; osum[1] *= corr[0];
        osum[2] *= corr[1]; osum[3] *= corr[1];

        const uint32_t m2_0 = packh2(mn[0], mn[0]);
        const uint32_t m2_1 = packh2(mn[1], mn[1]);
        uint32_t pa[4][4];
#pragma unroll
        for (int kk = 0; kk < 4; kk++) {
            pa[kk][0] = h2exp2sub(s[2 * kk][0],     s[2 * kk][1],     m2_0);
            pa[kk][1] = h2exp2sub(s[2 * kk][2],     s[2 * kk][3],     m2_1);
            pa[kk][2] = h2exp2sub(s[2 * kk + 1][0], s[2 * kk + 1][1], m2_0);
            pa[kk][3] = h2exp2sub(s[2 * kk + 1][2], s[2 * kk + 1][3], m2_1);
        }

        // ---- l += P @ 1 (tensor pipe) ----
#pragma unroll
        for (int kk = 0; kk < 4; kk++)
            mma_f16(osum, pa[kk], ONE2, ONE2);

        // ---- O += P @ V ----
#pragma unroll
        for (int kk = 0; kk < 4; kk++) {
            uint32_t vb[16];
#pragma unroll
            for (int np = 0; np < 4; np++)
                ldsm4(vb + np * 4, vB + (np * 16 * KSTR + kk * 16) * 2);
#pragma unroll
            for (int nt = 0; nt < 8; nt++)
                mma_f16(o[nt], pa[kk], vb[nt * 2], vb[nt * 2 + 1]);
        }
    }

    // ---- normalize + write g_attnh ----
    const int b = bh >> 4;
    const int h = bh & 15;
    const float inv0 = 1.f / osum[0];
    const float inv1 = 1.f / osum[2];
    const int r0 = q0 + warp * 16 + g;
    __half* d0 = g_attnh + ((size_t)(b * S_ + r0))     * D_ + h * 64;
    __half* d1 = g_attnh + ((size_t)(b * S_ + r0 + 8)) * D_ + h * 64;
#pragma unroll
    for (int nt = 0; nt < 8; nt++) {
        const int col = nt * 8 + 2 * c;
        *(uint32_t*)(d0 + col) = packh2(o[nt][0] * inv0, o[nt][1] * inv0);
        *(uint32_t*)(d1 + col) = packh2(o[nt][2] * inv1, o[nt][3] * inv1);
    }
}

// ---------------------------------------------------------------------------
extern "C" void kernel_launch(void* const* d_in, const int* in_sizes, int n_in,
                              void* d_out, int out_size)
{
    const float* x     = (const float*)d_in[0];
    const float* w_qkv = (const float*)d_in[1];
    const float* b_qkv = (const float*)d_in[2];
    const float* w_out = (const float*)d_in[3];
    const float* b_out = (const float*)d_in[4];
    float* out = (float*)d_out;

    cudaFuncSetAttribute(gemm_h<1>, cudaFuncAttributeMaxDynamicSharedMemorySize, GEMM_SMEM);
    cudaFuncSetAttribute(gemm_h<2>, cudaFuncAttributeMaxDynamicSharedMemorySize, GEMM_SMEM);

    // 0) pre-pass
    conv_x<<<512, 256>>>(x, (M_ * D_) / 4);
    {
        dim3 blk(32, 8);
        transpose_conv<<<dim3((3 * D_) / 32, D_ / 32), blk>>>(w_qkv, 1, D_, 3 * D_);
        transpose_conv<<<dim3(D_ / 32, D_ / 32), blk>>>(w_out, 2, D_, D_);
    }
    // 1) QKV projection
    {
        dim3 grid((3 * D_) / 128, M_ / 128);
        gemm_h<1><<<grid, 256, GEMM_SMEM>>>(b_qkv, nullptr, M_, 3 * D_, D_);
    }
    // 2) flash attention
    {
        dim3 grid(S_ / 128, B_ * H_);
        attn_h<<<grid, 256>>>();
    }
    // 3) output projection
    {
        dim3 grid(D_ / 128, M_ / 128);
        gemm_h<2><<<grid, 256, GEMM_SMEM>>>(b_out, out, M_, D_, D_);
    }
}

// round 9
// speedup vs baseline: 8.5220x; 1.0163x over previous
#include <cuda_runtime.h>
#include <cuda_fp16.h>
#include <math.h>
#include <stdint.h>

#define B_  4
#define S_  2048
#define D_  1024
#define H_  16
#define HD_ 64
#define M_  (B_ * S_)
#define NT_ (S_ / 64)

// scale folded into Q: 1/sqrt(64) * log2(e)
#define QSC 0.18033688045f

// ---------------------------------------------------------------------------
// Scratch (__device__ globals; allocation-free rule). All fp16.
// ---------------------------------------------------------------------------
__device__ __half g_qh[(size_t)B_ * H_ * S_ * HD_];     // [b][h][s][hd], pre-scaled
__device__ __half g_kh[(size_t)B_ * H_ * S_ * HD_];     // [b][h][s][hd]
__device__ __half g_vth[(size_t)B_ * H_ * HD_ * S_];    // [b][h][hd][s]
__device__ __half g_attnh[(size_t)M_ * D_];             // [b*s][h*hd]
__device__ __half g_xh[(size_t)M_ * D_];
__device__ __half g_wqkvh[(size_t)3 * D_ * D_];         // w_qkv^T [3D][D]
__device__ __half g_wouth[(size_t)D_ * D_];             // w_out^T [D][D]

// ---------------------------------------------------------------------------
// helpers
// ---------------------------------------------------------------------------
__device__ __forceinline__ uint32_t saddr(const void* p)
{
    return (uint32_t)__cvta_generic_to_shared(p);
}
__device__ __forceinline__ void cpa16(uint32_t dst, const void* src)
{
    asm volatile("cp.async.cg.shared.global [%0], [%1], 16;\n" :: "r"(dst), "l"(src));
}
#define CP_COMMIT() asm volatile("cp.async.commit_group;\n")
#define CP_WAIT1()  asm volatile("cp.async.wait_group 1;\n")
#define CP_WAIT0()  asm volatile("cp.async.wait_group 0;\n")

__device__ __forceinline__ void ldsm4(uint32_t* r, uint32_t addr)
{
    asm volatile("ldmatrix.sync.aligned.m8n8.x4.shared.b16 {%0,%1,%2,%3}, [%4];"
                 : "=r"(r[0]), "=r"(r[1]), "=r"(r[2]), "=r"(r[3]) : "r"(addr));
}

__device__ __forceinline__ void mma_f16(float* c, const uint32_t* a,
                                        uint32_t b0, uint32_t b1)
{
    asm volatile(
        "mma.sync.aligned.m16n8k16.row.col.f32.f16.f16.f32 "
        "{%0,%1,%2,%3}, {%4,%5,%6,%7}, {%8,%9}, {%0,%1,%2,%3};"
        : "+f"(c[0]), "+f"(c[1]), "+f"(c[2]), "+f"(c[3])
        : "r"(a[0]), "r"(a[1]), "r"(a[2]), "r"(a[3]), "r"(b0), "r"(b1));
}

__device__ __forceinline__ uint32_t packh2(float lo, float hi)
{
    __half2 h = __floats2half2_rn(lo, hi);
    return *(uint32_t*)&h;
}
__device__ __forceinline__ float ex2f(float x)
{
    float y;
    asm("ex2.approx.f32 %0, %1;" : "=f"(y) : "f"(x));
    return y;
}
__device__ __forceinline__ uint32_t h2exp2sub(float lo, float hi, uint32_t m2)
{
    uint32_t s2 = packh2(lo, hi);
    uint32_t d, r;
    asm("sub.f16x2 %0, %1, %2;" : "=r"(d) : "r"(s2), "r"(m2));
    asm("ex2.approx.f16x2 %0, %1;" : "=r"(r) : "r"(d));
    return r;
}

// ---------------------------------------------------------------------------
// pre-pass: x -> fp16; weights -> transposed fp16 [N][K]
// ---------------------------------------------------------------------------
__global__ void conv_x(const float* __restrict__ src, int n4)
{
    for (int i = blockIdx.x * blockDim.x + threadIdx.x; i < n4;
         i += gridDim.x * blockDim.x) {
        float4 v = ((const float4*)src)[i];
        uint2 o;
        o.x = packh2(v.x, v.y);
        o.y = packh2(v.z, v.w);
        ((uint2*)g_xh)[i] = o;
    }
}

__global__ void transpose_conv(const float* __restrict__ src, int which,
                               int K, int N)
{
    __shared__ float t[32][33];
    __half* dst = (which == 1) ? g_wqkvh : g_wouth;
    const int nx = blockIdx.x * 32, ky = blockIdx.y * 32;
    const int tx = threadIdx.x, ty = threadIdx.y;
#pragma unroll
    for (int j = 0; j < 32; j += 8)
        t[ty + j][tx] = src[(size_t)(ky + ty + j) * N + nx + tx];
    __syncthreads();
#pragma unroll
    for (int j = 0; j < 32; j += 8)
        dst[(size_t)(nx + ty + j) * K + ky + tx] = __float2half(t[tx][ty + j]);
}

// ---------------------------------------------------------------------------
// fp16 mma GEMM: C[M,N] = A[M,K] @ Bt[N,K]^T + bias
// 128x128 block, BK=64, 256 threads, warp 64x32. 3-stage cp.async:
// loads run TWO chunks ahead; one barrier per chunk.
// smem stride 72 halves (LDSM conflict-free).
// ---------------------------------------------------------------------------
#define ASTR 72
#define GTILE (128 * ASTR)                       // halves per matrix per stage
#define GEMM_SMEM (3 * 2 * GTILE * 2)            // 110592 B

template <int EPI>
__global__ __launch_bounds__(256, 2)
void gemm_h(const float* __restrict__ bias, float* __restrict__ C,
            int Mn, int Nn, int Kn)
{
    extern __shared__ __half gsm[];
    __half* sA = gsm;                            // [3][128][ASTR]
    __half* sB = gsm + 3 * GTILE;                // [3][128][ASTR]

    const __half* A  = (EPI == 1) ? g_xh : g_attnh;
    const __half* Bt = (EPI == 1) ? g_wqkvh : g_wouth;

    const int tid  = threadIdx.x;
    const int warp = tid >> 5;
    const int lane = tid & 31;
    const int wm   = warp >> 2;
    const int wn   = warp & 3;
    const int g    = lane >> 2;
    const int c    = lane & 3;
    const int bm   = blockIdx.y * 128;
    const int bn   = blockIdx.x * 128;

    const int a_r = lane & 15;
    const int a_c = (lane >> 4) << 3;
    const int b_r = (lane & 7) + ((lane >> 4) << 3);
    const int b_c = ((lane >> 3) & 1) << 3;

    float acc[4][4][4];
#pragma unroll
    for (int mi = 0; mi < 4; mi++)
#pragma unroll
        for (int ni = 0; ni < 4; ni++)
#pragma unroll
            for (int e = 0; e < 4; e++) acc[mi][ni][e] = 0.f;

    auto load_chunk = [&](int kc, int buf) {
        __half* dA = sA + buf * GTILE;
        __half* dB = sB + buf * GTILE;
#pragma unroll
        for (int p = 0; p < 4; p++) {
            int id = tid + p * 256;              // 0..1023
            int r  = id >> 3;
            int ch = id & 7;
            cpa16(saddr(dA + r * ASTR + ch * 8), A  + (size_t)(bm + r) * Kn + kc * 64 + ch * 8);
            cpa16(saddr(dB + r * ASTR + ch * 8), Bt + (size_t)(bn + r) * Kn + kc * 64 + ch * 8);
        }
    };

    const int NCH = Kn / 64;                     // 16
    load_chunk(0, 0); CP_COMMIT();
    load_chunk(1, 1); CP_COMMIT();

    int buf = 0;
    for (int it = 0; it < NCH; it++) {
        if (it + 1 < NCH) { CP_WAIT1(); } else { CP_WAIT0(); }
        __syncthreads();                         // chunk it ready; all warps past it-1
        if (it + 2 < NCH) {
            int nb = buf + 2; if (nb >= 3) nb -= 3;
            load_chunk(it + 2, nb);
            CP_COMMIT();
        }
        const uint32_t aB = saddr(sA + buf * GTILE + (wm * 64 + a_r) * ASTR + a_c);
        const uint32_t bB = saddr(sB + buf * GTILE + (wn * 32 + b_r) * ASTR + b_c);
#pragma unroll
        for (int kk = 0; kk < 4; kk++) {
            uint32_t af[4][4];
            uint32_t bfr[8];
#pragma unroll
            for (int mi = 0; mi < 4; mi++)
                ldsm4(af[mi], aB + (mi * 16 * ASTR + kk * 16) * 2);
#pragma unroll
            for (int np = 0; np < 2; np++)
                ldsm4(bfr + np * 4, bB + (np * 16 * ASTR + kk * 16) * 2);
#pragma unroll
            for (int mi = 0; mi < 4; mi++)
#pragma unroll
                for (int ni = 0; ni < 4; ni++)
                    mma_f16(acc[mi][ni], af[mi], bfr[ni * 2], bfr[ni * 2 + 1]);
        }
        if (++buf == 3) buf = 0;
    }

    // ---- epilogue ----
#pragma unroll
    for (int mi = 0; mi < 4; mi++) {
        const int r0 = bm + wm * 64 + mi * 16 + g;
        const int r1 = r0 + 8;
#pragma unroll
        for (int ni = 0; ni < 4; ni++) {
            const int col0 = bn + wn * 32 + ni * 8 + 2 * c;
            const float bv0 = __ldg(bias + col0);
            const float bv1 = __ldg(bias + col0 + 1);
            float v00 = acc[mi][ni][0] + bv0;
            float v01 = acc[mi][ni][1] + bv1;
            float v10 = acc[mi][ni][2] + bv0;
            float v11 = acc[mi][ni][3] + bv1;
            if (EPI == 2) {
                *(float2*)(C + (size_t)r0 * Nn + col0) = make_float2(v00, v01);
                *(float2*)(C + (size_t)r1 * Nn + col0) = make_float2(v10, v11);
            } else {
                const int which = col0 >> 10;
                const int d0 = col0 & 1023;
                const int h  = d0 >> 6;
                const int hd = d0 & 63;
                const int b  = r0 >> 11;
                const int s0 = r0 & 2047;
                const int s1 = r1 & 2047;
                if (which == 0) {                // Q: fold softmax scale (log2 dom)
                    v00 *= QSC; v01 *= QSC; v10 *= QSC; v11 *= QSC;
                    const size_t base = (((size_t)b * H_ + h) * S_);
                    *(uint32_t*)(g_qh + (base + s0) * HD_ + hd) = packh2(v00, v01);
                    *(uint32_t*)(g_qh + (base + s1) * HD_ + hd) = packh2(v10, v11);
                } else if (which == 1) {
                    const size_t base = (((size_t)b * H_ + h) * S_);
                    *(uint32_t*)(g_kh + (base + s0) * HD_ + hd) = packh2(v00, v01);
                    *(uint32_t*)(g_kh + (base + s1) * HD_ + hd) = packh2(v10, v11);
                } else {
                    const size_t base = (((size_t)b * H_ + h) * HD_);
                    g_vth[(base + hd)     * S_ + s0] = __float2half(v00);
                    g_vth[(base + hd + 1) * S_ + s0] = __float2half(v01);
                    g_vth[(base + hd)     * S_ + s1] = __float2half(v10);
                    g_vth[(base + hd + 1) * S_ + s1] = __float2half(v11);
                }
            }
        }
    }
}

// ---------------------------------------------------------------------------
// Flash attention, fp16 m16n8k16 + ldmatrix, log2-domain softmax,
// f16x2 exp, l via ones-MMA. 3-stage cp.async (loads two tiles ahead).
// Q tile 128, KV tile 64, HD 64; 8 warps.
// ---------------------------------------------------------------------------
#define KSTR 72
#define KVT (64 * KSTR)                          // halves per K (or V) stage
#define ATT_SMEM (3 * 2 * KVT * 2)               // 55296 B
#define ONE2 0x3C003C00u

__global__ __launch_bounds__(256, 2)
void attn_h()
{
    extern __shared__ __half asm_[];
    __half* sK = asm_;                           // [3][64][KSTR]
    __half* sV = asm_ + 3 * KVT;                 // [3][64][KSTR]

    const int tid  = threadIdx.x;
    const int warp = tid >> 5;
    const int lane = tid & 31;
    const int g    = lane >> 2;
    const int c    = lane & 3;
    const int bh   = blockIdx.y;
    const int q0   = blockIdx.x * 128;

    const __half* Kp  = g_kh  + (size_t)bh * S_ * HD_;
    const __half* Vtp = g_vth + (size_t)bh * HD_ * S_;

    const int b_r = (lane & 7) + ((lane >> 4) << 3);
    const int b_c = ((lane >> 3) & 1) << 3;

    // ---- Q fragments straight from gmem (pre-scaled by QSC) ----
    uint32_t qa[4][4];
    {
        const int r0 = q0 + warp * 16 + g;
        const uint32_t* Q0 = (const uint32_t*)(g_qh + ((size_t)bh * S_ + r0) * HD_) + c;
        const uint32_t* Q1 = (const uint32_t*)(g_qh + ((size_t)bh * S_ + r0 + 8) * HD_) + c;
#pragma unroll
        for (int kk = 0; kk < 4; kk++) {
            qa[kk][0] = Q0[kk * 8];
            qa[kk][1] = Q1[kk * 8];
            qa[kk][2] = Q0[kk * 8 + 4];
            qa[kk][3] = Q1[kk * 8 + 4];
        }
    }

    float o[8][4];
#pragma unroll
    for (int nt = 0; nt < 8; nt++)
#pragma unroll
        for (int e = 0; e < 4; e++) o[nt][e] = 0.f;
    float osum[4] = {0.f, 0.f, 0.f, 0.f};
    float mrow[2] = {-1e30f, -1e30f};

    auto issue_kv = [&](int kt, int bufi) {
        __half* dK = sK + bufi * KVT;
        __half* dV = sV + bufi * KVT;
#pragma unroll
        for (int p = 0; p < 2; p++) {
            int id = tid + p * 256;
            int r  = id >> 3;
            int ch = id & 7;
            cpa16(saddr(dK + r * KSTR + ch * 8), Kp  + (size_t)(kt * 64 + r) * HD_ + ch * 8);
            cpa16(saddr(dV + r * KSTR + ch * 8), Vtp + (size_t)r * S_ + kt * 64 + ch * 8);
        }
    };

    issue_kv(0, 0); CP_COMMIT();
    issue_kv(1, 1); CP_COMMIT();

    int bufi = 0;
    for (int kt = 0; kt < NT_; kt++) {
        if (kt + 1 < NT_) { CP_WAIT1(); } else { CP_WAIT0(); }
        __syncthreads();                         // tile kt ready; all warps past kt-1
        if (kt + 2 < NT_) {
            int nb = bufi + 2; if (nb >= 3) nb -= 3;
            issue_kv(kt + 2, nb);
            CP_COMMIT();
        }
        const uint32_t kB = saddr(sK + bufi * KVT + b_r * KSTR + b_c);
        const uint32_t vB = saddr(sV + bufi * KVT + b_r * KSTR + b_c);

        // ---- S = Q @ K^T  (log2 units) ----
        float s[8][4];
#pragma unroll
        for (int nt = 0; nt < 8; nt++)
#pragma unroll
            for (int e = 0; e < 4; e++) s[nt][e] = 0.f;

#pragma unroll
        for (int kk = 0; kk < 4; kk++) {
            uint32_t kb[16];
#pragma unroll
            for (int np = 0; np < 4; np++)
                ldsm4(kb + np * 4, kB + (np * 16 * KSTR + kk * 16) * 2);
#pragma unroll
            for (int nt = 0; nt < 8; nt++)
                mma_f16(s[nt], qa[kk], kb[nt * 2], kb[nt * 2 + 1]);
        }

        // ---- online softmax: max + rescale (fp32), exp in f16x2 ----
        float mn[2], corr[2];
#pragma unroll
        for (int h = 0; h < 2; h++) {
            float tm = -1e30f;
#pragma unroll
            for (int nt = 0; nt < 8; nt++)
                tm = fmaxf(tm, fmaxf(s[nt][2 * h], s[nt][2 * h + 1]));
            tm = fmaxf(tm, __shfl_xor_sync(0xffffffffu, tm, 1));
            tm = fmaxf(tm, __shfl_xor_sync(0xffffffffu, tm, 2));
            mn[h]   = fmaxf(mrow[h], tm);
            corr[h] = ex2f(mrow[h] - mn[h]);
            mrow[h] = mn[h];
        }
#pragma unroll
        for (int nt = 0; nt < 8; nt++) {
            o[nt][0] *= corr[0]; o[nt][1] *= corr[0];
            o[nt][2] *= corr[1]; o[nt][3] *= corr[1];
        }
        osum[0] *= corr[0]; osum[1] *= corr[0];
        osum[2] *= corr[1]; osum[3] *= corr[1];

        const uint32_t m2_0 = packh2(mn[0], mn[0]);
        const uint32_t m2_1 = packh2(mn[1], mn[1]);
        uint32_t pa[4][4];
#pragma unroll
        for (int kk = 0; kk < 4; kk++) {
            pa[kk][0] = h2exp2sub(s[2 * kk][0],     s[2 * kk][1],     m2_0);
            pa[kk][1] = h2exp2sub(s[2 * kk][2],     s[2 * kk][3],     m2_1);
            pa[kk][2] = h2exp2sub(s[2 * kk + 1][0], s[2 * kk + 1][1], m2_0);
            pa[kk][3] = h2exp2sub(s[2 * kk + 1][2], s[2 * kk + 1][3], m2_1);
        }

        // ---- l += P @ 1 (tensor pipe) ----
#pragma unroll
        for (int kk = 0; kk < 4; kk++)
            mma_f16(osum, pa[kk], ONE2, ONE2);

        // ---- O += P @ V ----
#pragma unroll
        for (int kk = 0; kk < 4; kk++) {
            uint32_t vb[16];
#pragma unroll
            for (int np = 0; np < 4; np++)
                ldsm4(vb + np * 4, vB + (np * 16 * KSTR + kk * 16) * 2);
#pragma unroll
            for (int nt = 0; nt < 8; nt++)
                mma_f16(o[nt], pa[kk], vb[nt * 2], vb[nt * 2 + 1]);
        }
        if (++bufi == 3) bufi = 0;
    }

    // ---- normalize + write g_attnh ----
    const int b = bh >> 4;
    const int h = bh & 15;
    const float inv0 = 1.f / osum[0];
    const float inv1 = 1.f / osum[2];
    const int r0 = q0 + warp * 16 + g;
    __half* d0 = g_attnh + ((size_t)(b * S_ + r0))     * D_ + h * 64;
    __half* d1 = g_attnh + ((size_t)(b * S_ + r0 + 8)) * D_ + h * 64;
#pragma unroll
    for (int nt = 0; nt < 8; nt++) {
        const int col = nt * 8 + 2 * c;
        *(uint32_t*)(d0 + col) = packh2(o[nt][0] * inv0, o[nt][1] * inv0);
        *(uint32_t*)(d1 + col) = packh2(o[nt][2] * inv1, o[nt][3] * inv1);
    }
}

// ---------------------------------------------------------------------------
extern "C" void kernel_launch(void* const* d_in, const int* in_sizes, int n_in,
                              void* d_out, int out_size)
{
    const float* x     = (const float*)d_in[0];
    const float* w_qkv = (const float*)d_in[1];
    const float* b_qkv = (const float*)d_in[2];
    const float* w_out = (const float*)d_in[3];
    const float* b_out = (const float*)d_in[4];
    float* out = (float*)d_out;

    cudaFuncSetAttribute(gemm_h<1>, cudaFuncAttributeMaxDynamicSharedMemorySize, GEMM_SMEM);
    cudaFuncSetAttribute(gemm_h<2>, cudaFuncAttributeMaxDynamicSharedMemorySize, GEMM_SMEM);
    cudaFuncSetAttribute(attn_h,    cudaFuncAttributeMaxDynamicSharedMemorySize, ATT_SMEM);

    // 0) pre-pass
    conv_x<<<512, 256>>>(x, (M_ * D_) / 4);
    {
        dim3 blk(32, 8);
        transpose_conv<<<dim3((3 * D_) / 32, D_ / 32), blk>>>(w_qkv, 1, D_, 3 * D_);
        transpose_conv<<<dim3(D_ / 32, D_ / 32), blk>>>(w_out, 2, D_, D_);
    }
    // 1) QKV projection
    {
        dim3 grid((3 * D_) / 128, M_ / 128);
        gemm_h<1><<<grid, 256, GEMM_SMEM>>>(b_qkv, nullptr, M_, 3 * D_, D_);
    }
    // 2) flash attention
    {
        dim3 grid(S_ / 128, B_ * H_);
        attn_h<<<grid, 256, ATT_SMEM>>>();
    }
    // 3) output projection
    {
        dim3 grid(D_ / 128, M_ / 128);
        gemm_h<2><<<grid, 256, GEMM_SMEM>>>(b_out, out, M_, D_, D_);
    }
}